// round 9
// baseline (speedup 1.0000x reference)
#include <cuda_runtime.h>
#include <cuda_bf16.h>
#include <math.h>
#include <stdint.h>

// Problem constants
#define M_TOK 16384      // BATCH * L
#define D_IN  1024
#define NF    356        // 256 (B) + 4 (X) + 64 (decay) + 32 (theta)
#define NFP   384        // padded feature count
#define NRF   256        // N * R
#define NN    64
#define RR    4
#define LL    4096
#define BBATCH 4

// ---------------------------------------------------------------------------
// Scratch (device globals: no runtime allocation allowed)
// ---------------------------------------------------------------------------
__device__ __nv_bfloat16 g_xhi[(size_t)M_TOK * D_IN];
__device__ __nv_bfloat16 g_xlo[(size_t)M_TOK * D_IN];
__device__ __nv_bfloat16 g_Whi[(size_t)NFP * D_IN];
__device__ __nv_bfloat16 g_Wlo[(size_t)NFP * D_IN];
__device__ __nv_bfloat16 g_Fhi[(size_t)M_TOK * NRF];
__device__ __nv_bfloat16 g_Flo[(size_t)M_TOK * NRF];
__device__ __nv_bfloat16 g_Wohi[(size_t)D_IN * NRF];
__device__ __nv_bfloat16 g_Wolo[(size_t)D_IN * NRF];
__device__ float g_P[(size_t)M_TOK * NFP];
__device__ float g_bcat[NFP];
__device__ float g_Hscratch[(size_t)BBATCH * RR * LL * NN];

// ---------------------------------------------------------------------------
// PTX helpers (base sm_103 target: mma.sync + ldmatrix + cp.async only)
// ---------------------------------------------------------------------------
__device__ __forceinline__ uint32_t smem_u32(const void* p) {
    uint32_t a;
    asm("{ .reg .u64 t; cvta.to.shared.u64 t, %1; cvt.u32.u64 %0, t; }" : "=r"(a) : "l"(p));
    return a;
}

#define CP_ASYNC16(saddr, gptr) \
    asm volatile("cp.async.cg.shared.global [%0], [%1], 16;" :: "r"(saddr), "l"(gptr) : "memory")
#define CP_COMMIT() asm volatile("cp.async.commit_group;" ::: "memory")
#define CP_WAIT1()  asm volatile("cp.async.wait_group 1;" ::: "memory")
#define CP_WAIT0()  asm volatile("cp.async.wait_group 0;" ::: "memory")

__device__ __forceinline__ void ldm_x4(uint32_t* r, uint32_t addr) {
    asm volatile("ldmatrix.sync.aligned.m8n8.x4.shared.b16 {%0,%1,%2,%3}, [%4];"
                 : "=r"(r[0]), "=r"(r[1]), "=r"(r[2]), "=r"(r[3]) : "r"(addr));
}
__device__ __forceinline__ void mma16816(float* c, const uint32_t* a, const uint32_t* b) {
    asm volatile(
        "mma.sync.aligned.m16n8k16.row.col.f32.bf16.bf16.f32 "
        "{%0,%1,%2,%3}, {%4,%5,%6,%7}, {%8,%9}, {%0,%1,%2,%3};"
        : "+f"(c[0]), "+f"(c[1]), "+f"(c[2]), "+f"(c[3])
        : "r"(a[0]), "r"(a[1]), "r"(a[2]), "r"(a[3]), "r"(b[0]), "r"(b[1]));
}

// ---------------------------------------------------------------------------
// Split fp32 -> (hi, lo) bf16
// ---------------------------------------------------------------------------
__global__ void split_kernel(const float* __restrict__ src,
                             __nv_bfloat16* __restrict__ hi,
                             __nv_bfloat16* __restrict__ lo, int n4) {
    int i = blockIdx.x * blockDim.x + threadIdx.x;
    if (i >= n4) return;
    float4 v = reinterpret_cast<const float4*>(src)[i];
    __nv_bfloat16 h0 = __float2bfloat16(v.x), h1 = __float2bfloat16(v.y);
    __nv_bfloat16 h2 = __float2bfloat16(v.z), h3 = __float2bfloat16(v.w);
    __nv_bfloat162 H01; H01.x = h0; H01.y = h1;
    __nv_bfloat162 H23; H23.x = h2; H23.y = h3;
    __nv_bfloat162 L01, L23;
    L01.x = __float2bfloat16(v.x - __bfloat162float(h0));
    L01.y = __float2bfloat16(v.y - __bfloat162float(h1));
    L23.x = __float2bfloat16(v.z - __bfloat162float(h2));
    L23.y = __float2bfloat16(v.w - __bfloat162float(h3));
    reinterpret_cast<__nv_bfloat162*>(hi)[2 * i]     = H01;
    reinterpret_cast<__nv_bfloat162*>(hi)[2 * i + 1] = H23;
    reinterpret_cast<__nv_bfloat162*>(lo)[2 * i]     = L01;
    reinterpret_cast<__nv_bfloat162*>(lo)[2 * i + 1] = L23;
}

// ---------------------------------------------------------------------------
// Pack + split the four projection weight matrices into g_Whi/g_Wlo + g_bcat
// ---------------------------------------------------------------------------
__global__ void pack_split_kernel(const float* __restrict__ W_B, const float* __restrict__ b_B,
                                  const float* __restrict__ W_X, const float* __restrict__ b_X,
                                  const float* __restrict__ W_d, const float* __restrict__ b_d,
                                  const float* __restrict__ W_t, const float* __restrict__ b_t) {
    int idx = blockIdx.x * blockDim.x + threadIdx.x;
    const int total = NFP * D_IN;
    for (int i = idx; i < total; i += gridDim.x * blockDim.x) {
        int f = i >> 10, k = i & 1023;
        float v = 0.f;
        if      (f < 256) v = W_B[f * D_IN + k];
        else if (f < 260) v = W_X[(f - 256) * D_IN + k];
        else if (f < 324) v = W_d[(f - 260) * D_IN + k];
        else if (f < 356) v = W_t[(f - 324) * D_IN + k];
        __nv_bfloat16 h = __float2bfloat16(v);
        g_Whi[i] = h;
        g_Wlo[i] = __float2bfloat16(v - __bfloat162float(h));
    }
    if (idx < NFP) {
        float v = 0.f;
        if      (idx < 256) v = b_B[idx];
        else if (idx < 260) v = b_X[idx - 256];
        else if (idx < 324) v = b_d[idx - 260];
        else if (idx < 356) v = b_t[idx - 324];
        g_bcat[idx] = v;
    }
}

// ---------------------------------------------------------------------------
// HMMA split-bf16 GEMM: C[m][n] = sum_k A[m,k]*B[n,k]
// 3-term: Ahi*Bhi + Ahi*Blo + Alo*Bhi.  Tile 128x128, BK=32, 256 threads.
// 3-stage cp.async ring (one __syncthreads per K-block). Rows padded to
// 80 B -> ldmatrix conflict-free. Warp grid 2(M) x 4(N), warp tile 64x32.
// MMA order: pass-outer, 16 independent MMAs between accumulator reuses.
// ---------------------------------------------------------------------------
#define ROWB 80                       // padded row stride in bytes (40 bf16)
#define TILEB (128 * ROWB)            // 10240 bytes per (matrix, half)
#define STAGEB (4 * TILEB)            // Ahi, Alo, Bhi, Blo = 40960 bytes
#define NSTAGE 3

template<bool SILU>
__global__ __launch_bounds__(256, 1)
void mma_gemm(const __nv_bfloat16* __restrict__ Ahi, const __nv_bfloat16* __restrict__ Alo,
              const __nv_bfloat16* __restrict__ Bhi, const __nv_bfloat16* __restrict__ Blo,
              const float* __restrict__ bias, float* __restrict__ C, int K, int ldc) {
    extern __shared__ __align__(128) char smem[];
    const uint32_t sb = smem_u32(smem);

    const int tid = threadIdx.x;
    const int wid = tid >> 5, lane = tid & 31;
    const int wm = wid & 1;            // 0..1  (M)
    const int wn = wid >> 1;           // 0..3  (N)
    const int m0 = blockIdx.x * 128, n0 = blockIdx.y * 128;

    // cp.async per-thread chunk coords (512 16B-chunks per (matrix,half)/stage)
    const int c0r = tid >> 2,         c0k = tid & 3;
    const int c1r = (tid + 256) >> 2, c1k = tid & 3;

    // ldmatrix lane addressing
    const int a_row = (lane & 7) + ((lane >> 3) & 1) * 8;   // 0..15
    const int a_kc  = lane >> 4;                            // 0..1
    const uint32_t a_base = (uint32_t)((wm * 64 + a_row) * ROWB + a_kc * 16);
    // packed-B x4: mats {j,k0},{j,k8},{j+1,k0},{j+1,k8}
    const int b_prow = (lane & 7) + ((lane >> 4) << 3);     // 0..15
    const int b_kc2  = (lane >> 3) & 1;
    const uint32_t b_base = (uint32_t)((wn * 32 + b_prow) * ROWB + b_kc2 * 16);

    float acc[4][4][4];
    #pragma unroll
    for (int i = 0; i < 4; i++)
        #pragma unroll
        for (int j = 0; j < 4; j++)
            #pragma unroll
            for (int q = 0; q < 4; q++) acc[i][j][q] = 0.f;

    const int nkb = K >> 5;

    auto load_stage = [&](int kb, int stage) {
        const uint32_t s0 = sb + stage * STAGEB;
        const int kofs = kb << 5;
        {
            size_t ga = (size_t)(m0 + c0r) * K + kofs + c0k * 8;
            size_t gb = (size_t)(n0 + c0r) * K + kofs + c0k * 8;
            uint32_t so = (uint32_t)(c0r * ROWB + c0k * 16);
            CP_ASYNC16(s0 + 0 * TILEB + so, Ahi + ga);
            CP_ASYNC16(s0 + 1 * TILEB + so, Alo + ga);
            CP_ASYNC16(s0 + 2 * TILEB + so, Bhi + gb);
            CP_ASYNC16(s0 + 3 * TILEB + so, Blo + gb);
        }
        {
            size_t ga = (size_t)(m0 + c1r) * K + kofs + c1k * 8;
            size_t gb = (size_t)(n0 + c1r) * K + kofs + c1k * 8;
            uint32_t so = (uint32_t)(c1r * ROWB + c1k * 16);
            CP_ASYNC16(s0 + 0 * TILEB + so, Ahi + ga);
            CP_ASYNC16(s0 + 1 * TILEB + so, Alo + ga);
            CP_ASYNC16(s0 + 2 * TILEB + so, Bhi + gb);
            CP_ASYNC16(s0 + 3 * TILEB + so, Blo + gb);
        }
    };

    // Prologue: 2 stages in flight
    load_stage(0, 0); CP_COMMIT();
    if (nkb > 1) { load_stage(1, 1); CP_COMMIT(); }

    int stage = 0;
    for (int kb = 0; kb < nkb; kb++) {
        if (kb == nkb - 1) { CP_WAIT0(); } else { CP_WAIT1(); }
        __syncthreads();
        // refill the stage freed at kb-1 (all warps are past its compute)
        if (kb + 2 < nkb) {
            int ns = stage + 2; if (ns >= NSTAGE) ns -= NSTAGE;
            load_stage(kb + 2, ns);
            CP_COMMIT();
        }

        const uint32_t s0 = sb + stage * STAGEB;
        #pragma unroll
        for (int s = 0; s < 2; s++) {          // two k16 steps per BK=32
            uint32_t ah[4][4], al[4][4], bh[4][2], bl[4][2];
            #pragma unroll
            for (int i = 0; i < 4; i++) {
                uint32_t ao = s0 + a_base + (uint32_t)(i * 16 * ROWB + s * 32);
                ldm_x4(ah[i], ao);
                ldm_x4(al[i], ao + TILEB);
            }
            #pragma unroll
            for (int jj = 0; jj < 4; jj += 2) {
                uint32_t bo = s0 + 2 * TILEB + b_base + (uint32_t)(jj * 8 * ROWB + s * 32);
                uint32_t t4[4];
                ldm_x4(t4, bo);
                bh[jj][0] = t4[0]; bh[jj][1] = t4[1];
                bh[jj + 1][0] = t4[2]; bh[jj + 1][1] = t4[3];
                ldm_x4(t4, bo + TILEB);
                bl[jj][0] = t4[0]; bl[jj][1] = t4[1];
                bl[jj + 1][0] = t4[2]; bl[jj + 1][1] = t4[3];
            }
            // pass-outer: 16 independent MMAs between accumulator RAW reuses
            #pragma unroll
            for (int i = 0; i < 4; i++)
                #pragma unroll
                for (int j = 0; j < 4; j++)
                    mma16816(acc[i][j], ah[i], bh[j]);
            #pragma unroll
            for (int i = 0; i < 4; i++)
                #pragma unroll
                for (int j = 0; j < 4; j++)
                    mma16816(acc[i][j], al[i], bh[j]);
            #pragma unroll
            for (int i = 0; i < 4; i++)
                #pragma unroll
                for (int j = 0; j < 4; j++)
                    mma16816(acc[i][j], ah[i], bl[j]);
        }
        stage++; if (stage >= NSTAGE) stage = 0;
    }

    // Epilogue
    const int tr = lane >> 2;            // 0..7
    const int tc = (lane & 3) * 2;       // 0,2,4,6
    #pragma unroll
    for (int i = 0; i < 4; i++) {
        #pragma unroll
        for (int j = 0; j < 4; j++) {
            int m = m0 + wm * 64 + i * 16 + tr;
            int n = n0 + wn * 32 + j * 8 + tc;
            float e0 = acc[i][j][0], e1 = acc[i][j][1];
            float e2 = acc[i][j][2], e3 = acc[i][j][3];
            if (SILU) {
                float bb0 = bias[n], bb1 = bias[n + 1];
                e0 += bb0; e1 += bb1; e2 += bb0; e3 += bb1;
                e0 = e0 / (1.f + __expf(-e0));
                e1 = e1 / (1.f + __expf(-e1));
                e2 = e2 / (1.f + __expf(-e2));
                e3 = e3 / (1.f + __expf(-e3));
            }
            float2* p0 = reinterpret_cast<float2*>(C + (size_t)m * ldc + n);
            float2* p1 = reinterpret_cast<float2*>(C + (size_t)(m + 8) * ldc + n);
            *p0 = make_float2(e0, e1);
            *p1 = make_float2(e2, e3);
        }
    }
}

// ---------------------------------------------------------------------------
// Elementwise: silu/sigmoid/rotary/decay*H -> H_new (fp32) + F split (bf16 hi/lo)
// ---------------------------------------------------------------------------
__global__ __launch_bounds__(256)
void elementwise_kernel(const float* __restrict__ H, const int* __restrict__ layer_idx,
                        float* __restrict__ Hnew,
                        __nv_bfloat16* __restrict__ Fhi, __nv_bfloat16* __restrict__ Flo) {
    const int token = blockIdx.x;
    const int b = token >> 12;
    const int l = token & 4095;
    const int t = threadIdx.x;

    __shared__ float sP[NF];
    __shared__ float sB[NRF];

    for (int i = t; i < NF; i += 256)
        sP[i] = g_P[(size_t)token * NFP + i] + g_bcat[i];
    __syncthreads();

    {
        float v = sP[t];
        sB[t] = v / (1.f + __expf(-v));
    }
    __syncthreads();

    const int r = t >> 6;
    const int n = t & 63;
    const int j = n >> 1;

    const float scale = (float)(*layer_idx + 1);
    const float th = sP[324 + j] * scale;
    float cs, sn;
    sincosf(th, &sn, &cs);

    const float x1 = sB[(n & ~1) * RR + r];
    const float x2 = sB[(n |  1) * RR + r];
    const float rot = (n & 1) ? (x1 * sn + x2 * cs) : (x1 * cs - x2 * sn);

    float xv = sP[256 + r];
    const float Xr = xv / (1.f + __expf(-xv));

    float dv = sP[260 + n];
    const float decay = 1.f / (1.f + __expf(-dv));

    const size_t hidx = (((size_t)(b * RR + r) * LL + l) * NN) + n;
    const float hnew = decay * H[hidx] + rot * Xr;

    Hnew[hidx] = hnew;

    __nv_bfloat16 h = __float2bfloat16(hnew);
    const size_t fidx = (size_t)token * NRF + (r * NN + n);
    Fhi[fidx] = h;
    Flo[fidx] = __float2bfloat16(hnew - __bfloat162float(h));
}

// ---------------------------------------------------------------------------
extern "C" void kernel_launch(void* const* d_in, const int* in_sizes, int n_in,
                              void* d_out, int out_size) {
    const float* x     = (const float*)d_in[0];
    const float* H     = (const float*)d_in[1];
    const float* W_B   = (const float*)d_in[2];
    const float* b_B   = (const float*)d_in[3];
    const float* W_X   = (const float*)d_in[4];
    const float* b_X   = (const float*)d_in[5];
    const float* W_d   = (const float*)d_in[6];
    const float* b_d   = (const float*)d_in[7];
    const float* W_t   = (const float*)d_in[8];
    const float* b_t   = (const float*)d_in[9];
    const float* W_out = (const float*)d_in[10];
    const float* b_out = (const float*)d_in[11];
    const int*   lidx  = (const int*)d_in[12];

    const size_t HE = (size_t)BBATCH * RR * LL * NN;   //  4,194,304
    const size_t OE = (size_t)BBATCH * LL * D_IN;      // 16,777,216

    float* hnew_dst;
    float* out_dst;
    if ((size_t)out_size >= HE + OE) {
        hnew_dst = (float*)d_out;
        out_dst  = (float*)d_out + HE;
    } else {
        cudaGetSymbolAddress((void**)&hnew_dst, g_Hscratch);
        out_dst  = (float*)d_out;
    }

    __nv_bfloat16 *xhi, *xlo, *Whi, *Wlo, *Fhi, *Flo, *Wohi, *Wolo;
    float* P_ptr;
    cudaGetSymbolAddress((void**)&xhi,  g_xhi);
    cudaGetSymbolAddress((void**)&xlo,  g_xlo);
    cudaGetSymbolAddress((void**)&Whi,  g_Whi);
    cudaGetSymbolAddress((void**)&Wlo,  g_Wlo);
    cudaGetSymbolAddress((void**)&Fhi,  g_Fhi);
    cudaGetSymbolAddress((void**)&Flo,  g_Flo);
    cudaGetSymbolAddress((void**)&Wohi, g_Wohi);
    cudaGetSymbolAddress((void**)&Wolo, g_Wolo);
    cudaGetSymbolAddress((void**)&P_ptr, g_P);

    const int SMEM_BYTES = NSTAGE * STAGEB;  // 122880
    cudaFuncSetAttribute(mma_gemm<false>, cudaFuncAttributeMaxDynamicSharedMemorySize, SMEM_BYTES);
    cudaFuncSetAttribute(mma_gemm<true>,  cudaFuncAttributeMaxDynamicSharedMemorySize, SMEM_BYTES);

    // 1) conversions / packing
    {
        int n4 = M_TOK * D_IN / 4;
        split_kernel<<<(n4 + 255) / 256, 256>>>(x, xhi, xlo, n4);
    }
    pack_split_kernel<<<768, 512>>>(W_B, b_B, W_X, b_X, W_d, b_d, W_t, b_t);
    {
        int n4 = D_IN * NRF / 4;
        split_kernel<<<(n4 + 255) / 256, 256>>>(W_out, Wohi, Wolo, n4);
    }

    // 2) projection GEMM: P[16384 x 384] = x @ Wcat^T  (HMMA split-bf16)
    mma_gemm<false><<<dim3(M_TOK / 128, NFP / 128), 256, SMEM_BYTES>>>(
        xhi, xlo, Whi, Wlo, nullptr, P_ptr, D_IN, NFP);

    // 3) elementwise -> H_new + F split
    elementwise_kernel<<<M_TOK, 256>>>(H, lidx, hnew_dst, Fhi, Flo);

    // 4) output GEMM: out[16384 x 1024] = silu(F @ W_out^T + b_out)
    mma_gemm<true><<<dim3(M_TOK / 128, D_IN / 128), 256, SMEM_BYTES>>>(
        Fhi, Flo, Wohi, Wolo, b_out, out_dst, NRF, D_IN);
}

// round 11
// speedup vs baseline: 1.0691x; 1.0691x over previous
#include <cuda_runtime.h>
#include <cuda_bf16.h>
#include <math.h>
#include <stdint.h>

// Problem constants
#define M_TOK 16384      // BATCH * L
#define D_IN  1024
#define NF    356        // 256 (B) + 4 (X) + 64 (decay) + 32 (theta)
#define NFP   384        // padded feature count
#define NRF   256        // N * R
#define NN    64
#define RR    4
#define LL    4096
#define BBATCH 4

// ---------------------------------------------------------------------------
// Scratch (device globals: no runtime allocation allowed)
// ---------------------------------------------------------------------------
__device__ __nv_bfloat16 g_xhi[(size_t)M_TOK * D_IN];
__device__ __nv_bfloat16 g_xlo[(size_t)M_TOK * D_IN];
__device__ __nv_bfloat16 g_Whi[(size_t)NFP * D_IN];
__device__ __nv_bfloat16 g_Wlo[(size_t)NFP * D_IN];
__device__ __nv_bfloat16 g_Fhi[(size_t)M_TOK * NRF];
__device__ __nv_bfloat16 g_Flo[(size_t)M_TOK * NRF];
__device__ __nv_bfloat16 g_Wohi[(size_t)D_IN * NRF];
__device__ __nv_bfloat16 g_Wolo[(size_t)D_IN * NRF];
__device__ float g_P[(size_t)M_TOK * NFP];
__device__ float g_bcat[NFP];
__device__ float g_Hscratch[(size_t)BBATCH * RR * LL * NN];

// ---------------------------------------------------------------------------
// PTX helpers (base sm_103 target: mma.sync + ldmatrix + cp.async only)
// ---------------------------------------------------------------------------
__device__ __forceinline__ uint32_t smem_u32(const void* p) {
    uint32_t a;
    asm("{ .reg .u64 t; cvta.to.shared.u64 t, %1; cvt.u32.u64 %0, t; }" : "=r"(a) : "l"(p));
    return a;
}

#define CP_ASYNC16(saddr, gptr) \
    asm volatile("cp.async.cg.shared.global [%0], [%1], 16;" :: "r"(saddr), "l"(gptr) : "memory")
#define CP_COMMIT() asm volatile("cp.async.commit_group;" ::: "memory")
#define CP_WAIT1()  asm volatile("cp.async.wait_group 1;" ::: "memory")
#define CP_WAIT0()  asm volatile("cp.async.wait_group 0;" ::: "memory")

__device__ __forceinline__ void ldm_x4(uint32_t* r, uint32_t addr) {
    asm volatile("ldmatrix.sync.aligned.m8n8.x4.shared.b16 {%0,%1,%2,%3}, [%4];"
                 : "=r"(r[0]), "=r"(r[1]), "=r"(r[2]), "=r"(r[3]) : "r"(addr));
}
__device__ __forceinline__ void mma16816(float* c, const uint32_t* a, const uint32_t* b) {
    asm volatile(
        "mma.sync.aligned.m16n8k16.row.col.f32.bf16.bf16.f32 "
        "{%0,%1,%2,%3}, {%4,%5,%6,%7}, {%8,%9}, {%0,%1,%2,%3};"
        : "+f"(c[0]), "+f"(c[1]), "+f"(c[2]), "+f"(c[3])
        : "r"(a[0]), "r"(a[1]), "r"(a[2]), "r"(a[3]), "r"(b[0]), "r"(b[1]));
}

// ---------------------------------------------------------------------------
// Split fp32 -> (hi, lo) bf16
// ---------------------------------------------------------------------------
__global__ void split_kernel(const float* __restrict__ src,
                             __nv_bfloat16* __restrict__ hi,
                             __nv_bfloat16* __restrict__ lo, int n4) {
    int i = blockIdx.x * blockDim.x + threadIdx.x;
    if (i >= n4) return;
    float4 v = reinterpret_cast<const float4*>(src)[i];
    __nv_bfloat16 h0 = __float2bfloat16(v.x), h1 = __float2bfloat16(v.y);
    __nv_bfloat16 h2 = __float2bfloat16(v.z), h3 = __float2bfloat16(v.w);
    __nv_bfloat162 H01; H01.x = h0; H01.y = h1;
    __nv_bfloat162 H23; H23.x = h2; H23.y = h3;
    __nv_bfloat162 L01, L23;
    L01.x = __float2bfloat16(v.x - __bfloat162float(h0));
    L01.y = __float2bfloat16(v.y - __bfloat162float(h1));
    L23.x = __float2bfloat16(v.z - __bfloat162float(h2));
    L23.y = __float2bfloat16(v.w - __bfloat162float(h3));
    reinterpret_cast<__nv_bfloat162*>(hi)[2 * i]     = H01;
    reinterpret_cast<__nv_bfloat162*>(hi)[2 * i + 1] = H23;
    reinterpret_cast<__nv_bfloat162*>(lo)[2 * i]     = L01;
    reinterpret_cast<__nv_bfloat162*>(lo)[2 * i + 1] = L23;
}

// ---------------------------------------------------------------------------
// Pack + split the four projection weight matrices into g_Whi/g_Wlo + g_bcat
// ---------------------------------------------------------------------------
__global__ void pack_split_kernel(const float* __restrict__ W_B, const float* __restrict__ b_B,
                                  const float* __restrict__ W_X, const float* __restrict__ b_X,
                                  const float* __restrict__ W_d, const float* __restrict__ b_d,
                                  const float* __restrict__ W_t, const float* __restrict__ b_t) {
    int idx = blockIdx.x * blockDim.x + threadIdx.x;
    const int total = NFP * D_IN;
    for (int i = idx; i < total; i += gridDim.x * blockDim.x) {
        int f = i >> 10, k = i & 1023;
        float v = 0.f;
        if      (f < 256) v = W_B[f * D_IN + k];
        else if (f < 260) v = W_X[(f - 256) * D_IN + k];
        else if (f < 324) v = W_d[(f - 260) * D_IN + k];
        else if (f < 356) v = W_t[(f - 324) * D_IN + k];
        __nv_bfloat16 h = __float2bfloat16(v);
        g_Whi[i] = h;
        g_Wlo[i] = __float2bfloat16(v - __bfloat162float(h));
    }
    if (idx < NFP) {
        float v = 0.f;
        if      (idx < 256) v = b_B[idx];
        else if (idx < 260) v = b_X[idx - 256];
        else if (idx < 324) v = b_d[idx - 260];
        else if (idx < 356) v = b_t[idx - 324];
        g_bcat[idx] = v;
    }
}

// ---------------------------------------------------------------------------
// HMMA split-bf16 GEMM: C[m][n] = sum_k A[m,k]*B[n,k]
// 3-term: Ahi*Bhi + Ahi*Blo + Alo*Bhi.  Tile 128x128, BK=32, 512 threads.
// Warp grid 4(M) x 4(N), warp tile 32x32 -> 4 warps/SMSP to cover latency.
// 3-stage cp.async ring; rows padded to 80 B -> ldmatrix conflict-free.
// ---------------------------------------------------------------------------
#define ROWB 80                       // padded row stride in bytes (40 bf16)
#define TILEB (128 * ROWB)            // 10240 bytes per (matrix, half)
#define STAGEB (4 * TILEB)            // Ahi, Alo, Bhi, Blo = 40960 bytes
#define NSTAGE 3

template<bool SILU>
__global__ __launch_bounds__(512, 1)
void mma_gemm(const __nv_bfloat16* __restrict__ Ahi, const __nv_bfloat16* __restrict__ Alo,
              const __nv_bfloat16* __restrict__ Bhi, const __nv_bfloat16* __restrict__ Blo,
              const float* __restrict__ bias, float* __restrict__ C, int K, int ldc) {
    extern __shared__ __align__(128) char smem[];
    const uint32_t sb = smem_u32(smem);

    const int tid = threadIdx.x;
    const int wid = tid >> 5, lane = tid & 31;
    const int wm = wid & 3;            // 0..3  (M)
    const int wn = wid >> 2;           // 0..3  (N)
    const int m0 = blockIdx.x * 128, n0 = blockIdx.y * 128;

    // cp.async: 512 chunks of 16B per (matrix,half) per stage; 1 chunk/thread/matrix
    const int cr = tid >> 2, ck = tid & 3;

    // ldmatrix lane addressing
    const int a_row = (lane & 7) + ((lane >> 3) & 1) * 8;   // 0..15
    const int a_kc  = lane >> 4;                            // 0..1
    const uint32_t a_base = (uint32_t)((wm * 32 + a_row) * ROWB + a_kc * 16);
    // packed-B x4: mats {j,k0},{j,k8},{j+1,k0},{j+1,k8}
    const int b_prow = (lane & 7) + ((lane >> 4) << 3);     // 0..15
    const int b_kc2  = (lane >> 3) & 1;
    const uint32_t b_base = (uint32_t)((wn * 32 + b_prow) * ROWB + b_kc2 * 16);

    float acc[2][4][4];
    #pragma unroll
    for (int i = 0; i < 2; i++)
        #pragma unroll
        for (int j = 0; j < 4; j++)
            #pragma unroll
            for (int q = 0; q < 4; q++) acc[i][j][q] = 0.f;

    const int nkb = K >> 5;

    auto load_stage = [&](int kb, int stage) {
        const uint32_t s0 = sb + stage * STAGEB;
        const int kofs = kb << 5;
        size_t ga = (size_t)(m0 + cr) * K + kofs + ck * 8;
        size_t gb = (size_t)(n0 + cr) * K + kofs + ck * 8;
        uint32_t so = (uint32_t)(cr * ROWB + ck * 16);
        CP_ASYNC16(s0 + 0 * TILEB + so, Ahi + ga);
        CP_ASYNC16(s0 + 1 * TILEB + so, Alo + ga);
        CP_ASYNC16(s0 + 2 * TILEB + so, Bhi + gb);
        CP_ASYNC16(s0 + 3 * TILEB + so, Blo + gb);
    };

    // Prologue: 2 stages in flight
    load_stage(0, 0); CP_COMMIT();
    if (nkb > 1) { load_stage(1, 1); CP_COMMIT(); }

    int stage = 0;
    for (int kb = 0; kb < nkb; kb++) {
        if (kb == nkb - 1) { CP_WAIT0(); } else { CP_WAIT1(); }
        __syncthreads();
        if (kb + 2 < nkb) {
            int ns = stage + 2; if (ns >= NSTAGE) ns -= NSTAGE;
            load_stage(kb + 2, ns);
            CP_COMMIT();
        }

        const uint32_t s0 = sb + stage * STAGEB;
        #pragma unroll
        for (int s = 0; s < 2; s++) {          // two k16 steps per BK=32
            uint32_t ah[2][4], al[2][4], bh[4][2], bl[4][2];
            #pragma unroll
            for (int i = 0; i < 2; i++) {
                uint32_t ao = s0 + a_base + (uint32_t)(i * 16 * ROWB + s * 32);
                ldm_x4(ah[i], ao);
                ldm_x4(al[i], ao + TILEB);
            }
            #pragma unroll
            for (int jj = 0; jj < 4; jj += 2) {
                uint32_t bo = s0 + 2 * TILEB + b_base + (uint32_t)(jj * 8 * ROWB + s * 32);
                uint32_t t4[4];
                ldm_x4(t4, bo);
                bh[jj][0] = t4[0]; bh[jj][1] = t4[1];
                bh[jj + 1][0] = t4[2]; bh[jj + 1][1] = t4[3];
                ldm_x4(t4, bo + TILEB);
                bl[jj][0] = t4[0]; bl[jj][1] = t4[1];
                bl[jj + 1][0] = t4[2]; bl[jj + 1][1] = t4[3];
            }
            // pass-outer: 8 independent MMAs between accumulator RAW reuses
            #pragma unroll
            for (int i = 0; i < 2; i++)
                #pragma unroll
                for (int j = 0; j < 4; j++)
                    mma16816(acc[i][j], ah[i], bh[j]);
            #pragma unroll
            for (int i = 0; i < 2; i++)
                #pragma unroll
                for (int j = 0; j < 4; j++)
                    mma16816(acc[i][j], al[i], bh[j]);
            #pragma unroll
            for (int i = 0; i < 2; i++)
                #pragma unroll
                for (int j = 0; j < 4; j++)
                    mma16816(acc[i][j], ah[i], bl[j]);
        }
        stage++; if (stage >= NSTAGE) stage = 0;
    }

    // Epilogue
    const int tr = lane >> 2;            // 0..7
    const int tc = (lane & 3) * 2;       // 0,2,4,6
    #pragma unroll
    for (int i = 0; i < 2; i++) {
        #pragma unroll
        for (int j = 0; j < 4; j++) {
            int m = m0 + wm * 32 + i * 16 + tr;
            int n = n0 + wn * 32 + j * 8 + tc;
            float e0 = acc[i][j][0], e1 = acc[i][j][1];
            float e2 = acc[i][j][2], e3 = acc[i][j][3];
            if (SILU) {
                float bb0 = bias[n], bb1 = bias[n + 1];
                e0 += bb0; e1 += bb1; e2 += bb0; e3 += bb1;
                e0 = e0 / (1.f + __expf(-e0));
                e1 = e1 / (1.f + __expf(-e1));
                e2 = e2 / (1.f + __expf(-e2));
                e3 = e3 / (1.f + __expf(-e3));
            }
            float2* p0 = reinterpret_cast<float2*>(C + (size_t)m * ldc + n);
            float2* p1 = reinterpret_cast<float2*>(C + (size_t)(m + 8) * ldc + n);
            *p0 = make_float2(e0, e1);
            *p1 = make_float2(e2, e3);
        }
    }
}

// ---------------------------------------------------------------------------
// Elementwise: silu/sigmoid/rotary/decay*H -> H_new (fp32) + F split (bf16 hi/lo)
// ---------------------------------------------------------------------------
__global__ __launch_bounds__(256)
void elementwise_kernel(const float* __restrict__ H, const int* __restrict__ layer_idx,
                        float* __restrict__ Hnew,
                        __nv_bfloat16* __restrict__ Fhi, __nv_bfloat16* __restrict__ Flo) {
    const int token = blockIdx.x;
    const int b = token >> 12;
    const int l = token & 4095;
    const int t = threadIdx.x;

    __shared__ float sP[NF];
    __shared__ float sB[NRF];

    for (int i = t; i < NF; i += 256)
        sP[i] = g_P[(size_t)token * NFP + i] + g_bcat[i];
    __syncthreads();

    {
        float v = sP[t];
        sB[t] = v / (1.f + __expf(-v));
    }
    __syncthreads();

    const int r = t >> 6;
    const int n = t & 63;
    const int j = n >> 1;

    const float scale = (float)(*layer_idx + 1);
    const float th = sP[324 + j] * scale;
    float cs, sn;
    sincosf(th, &sn, &cs);

    const float x1 = sB[(n & ~1) * RR + r];
    const float x2 = sB[(n |  1) * RR + r];
    const float rot = (n & 1) ? (x1 * sn + x2 * cs) : (x1 * cs - x2 * sn);

    float xv = sP[256 + r];
    const float Xr = xv / (1.f + __expf(-xv));

    float dv = sP[260 + n];
    const float decay = 1.f / (1.f + __expf(-dv));

    const size_t hidx = (((size_t)(b * RR + r) * LL + l) * NN) + n;
    const float hnew = decay * H[hidx] + rot * Xr;

    Hnew[hidx] = hnew;

    __nv_bfloat16 h = __float2bfloat16(hnew);
    const size_t fidx = (size_t)token * NRF + (r * NN + n);
    Fhi[fidx] = h;
    Flo[fidx] = __float2bfloat16(hnew - __bfloat162float(h));
}

// ---------------------------------------------------------------------------
extern "C" void kernel_launch(void* const* d_in, const int* in_sizes, int n_in,
                              void* d_out, int out_size) {
    const float* x     = (const float*)d_in[0];
    const float* H     = (const float*)d_in[1];
    const float* W_B   = (const float*)d_in[2];
    const float* b_B   = (const float*)d_in[3];
    const float* W_X   = (const float*)d_in[4];
    const float* b_X   = (const float*)d_in[5];
    const float* W_d   = (const float*)d_in[6];
    const float* b_d   = (const float*)d_in[7];
    const float* W_t   = (const float*)d_in[8];
    const float* b_t   = (const float*)d_in[9];
    const float* W_out = (const float*)d_in[10];
    const float* b_out = (const float*)d_in[11];
    const int*   lidx  = (const int*)d_in[12];

    const size_t HE = (size_t)BBATCH * RR * LL * NN;   //  4,194,304
    const size_t OE = (size_t)BBATCH * LL * D_IN;      // 16,777,216

    float* hnew_dst;
    float* out_dst;
    if ((size_t)out_size >= HE + OE) {
        hnew_dst = (float*)d_out;
        out_dst  = (float*)d_out + HE;
    } else {
        cudaGetSymbolAddress((void**)&hnew_dst, g_Hscratch);
        out_dst  = (float*)d_out;
    }

    __nv_bfloat16 *xhi, *xlo, *Whi, *Wlo, *Fhi, *Flo, *Wohi, *Wolo;
    float* P_ptr;
    cudaGetSymbolAddress((void**)&xhi,  g_xhi);
    cudaGetSymbolAddress((void**)&xlo,  g_xlo);
    cudaGetSymbolAddress((void**)&Whi,  g_Whi);
    cudaGetSymbolAddress((void**)&Wlo,  g_Wlo);
    cudaGetSymbolAddress((void**)&Fhi,  g_Fhi);
    cudaGetSymbolAddress((void**)&Flo,  g_Flo);
    cudaGetSymbolAddress((void**)&Wohi, g_Wohi);
    cudaGetSymbolAddress((void**)&Wolo, g_Wolo);
    cudaGetSymbolAddress((void**)&P_ptr, g_P);

    const int SMEM_BYTES = NSTAGE * STAGEB;  // 122880
    cudaFuncSetAttribute(mma_gemm<false>, cudaFuncAttributeMaxDynamicSharedMemorySize, SMEM_BYTES);
    cudaFuncSetAttribute(mma_gemm<true>,  cudaFuncAttributeMaxDynamicSharedMemorySize, SMEM_BYTES);

    // 1) conversions / packing
    {
        int n4 = M_TOK * D_IN / 4;
        split_kernel<<<(n4 + 255) / 256, 256>>>(x, xhi, xlo, n4);
    }
    pack_split_kernel<<<768, 512>>>(W_B, b_B, W_X, b_X, W_d, b_d, W_t, b_t);
    {
        int n4 = D_IN * NRF / 4;
        split_kernel<<<(n4 + 255) / 256, 256>>>(W_out, Wohi, Wolo, n4);
    }

    // 2) projection GEMM: P[16384 x 384] = x @ Wcat^T  (HMMA split-bf16)
    mma_gemm<false><<<dim3(M_TOK / 128, NFP / 128), 512, SMEM_BYTES>>>(
        xhi, xlo, Whi, Wlo, nullptr, P_ptr, D_IN, NFP);

    // 3) elementwise -> H_new + F split
    elementwise_kernel<<<M_TOK, 256>>>(H, lidx, hnew_dst, Fhi, Flo);

    // 4) output GEMM: out[16384 x 1024] = silu(F @ W_out^T + b_out)
    mma_gemm<true><<<dim3(M_TOK / 128, D_IN / 128), 512, SMEM_BYTES>>>(
        Fhi, Flo, Wohi, Wolo, b_out, out_dst, NRF, D_IN);
}

// round 14
// speedup vs baseline: 1.3382x; 1.2518x over previous
#include <cuda_runtime.h>
#include <cuda_fp16.h>
#include <math.h>
#include <stdint.h>

// Problem constants
#define M_TOK 16384      // BATCH * L
#define D_IN  1024
#define NF    356        // 256 (B) + 4 (X) + 64 (decay) + 32 (theta)
#define NFP   384        // padded feature count
#define NRF   256        // N * R
#define NN    64
#define RR    4
#define LL    4096
#define BBATCH 4

// ---------------------------------------------------------------------------
// Scratch (device globals: no runtime allocation allowed)
// ---------------------------------------------------------------------------
__device__ __half g_xh [(size_t)M_TOK * D_IN];    // x, single fp16
__device__ __half g_Whi[(size_t)NFP * D_IN];      // packed weights hi
__device__ __half g_Wlo[(size_t)NFP * D_IN];      // packed weights lo
__device__ __half g_Fh [(size_t)M_TOK * NRF];     // H_new flat, single fp16
__device__ __half g_Wohi[(size_t)D_IN * NRF];
__device__ __half g_Wolo[(size_t)D_IN * NRF];
__device__ float g_P[(size_t)M_TOK * NFP];
__device__ float g_bcat[NFP];
__device__ float g_Hscratch[(size_t)BBATCH * RR * LL * NN];

// ---------------------------------------------------------------------------
// PTX helpers (base sm_103 target: mma.sync + ldmatrix + cp.async only)
// ---------------------------------------------------------------------------
__device__ __forceinline__ uint32_t smem_u32(const void* p) {
    uint32_t a;
    asm("{ .reg .u64 t; cvta.to.shared.u64 t, %1; cvt.u32.u64 %0, t; }" : "=r"(a) : "l"(p));
    return a;
}

#define CP_ASYNC16(saddr, gptr) \
    asm volatile("cp.async.cg.shared.global [%0], [%1], 16;" :: "r"(saddr), "l"(gptr) : "memory")
#define CP_COMMIT() asm volatile("cp.async.commit_group;" ::: "memory")
#define CP_WAIT1()  asm volatile("cp.async.wait_group 1;" ::: "memory")
#define CP_WAIT0()  asm volatile("cp.async.wait_group 0;" ::: "memory")

__device__ __forceinline__ void ldm_x4(uint32_t* r, uint32_t addr) {
    asm volatile("ldmatrix.sync.aligned.m8n8.x4.shared.b16 {%0,%1,%2,%3}, [%4];"
                 : "=r"(r[0]), "=r"(r[1]), "=r"(r[2]), "=r"(r[3]) : "r"(addr));
}
__device__ __forceinline__ void mma16816(float* c, const uint32_t* a, const uint32_t* b) {
    asm volatile(
        "mma.sync.aligned.m16n8k16.row.col.f32.f16.f16.f32 "
        "{%0,%1,%2,%3}, {%4,%5,%6,%7}, {%8,%9}, {%0,%1,%2,%3};"
        : "+f"(c[0]), "+f"(c[1]), "+f"(c[2]), "+f"(c[3])
        : "r"(a[0]), "r"(a[1]), "r"(a[2]), "r"(a[3]), "r"(b[0]), "r"(b[1]));
}

// ---------------------------------------------------------------------------
// Convert fp32 -> fp16 (single plane)
// ---------------------------------------------------------------------------
__global__ void conv_half_kernel(const float* __restrict__ src,
                                 __half* __restrict__ dst, int n4) {
    int i = blockIdx.x * blockDim.x + threadIdx.x;
    if (i >= n4) return;
    float4 v = reinterpret_cast<const float4*>(src)[i];
    __half2 a = __floats2half2_rn(v.x, v.y);
    __half2 b = __floats2half2_rn(v.z, v.w);
    reinterpret_cast<__half2*>(dst)[2 * i]     = a;
    reinterpret_cast<__half2*>(dst)[2 * i + 1] = b;
}

// ---------------------------------------------------------------------------
// Split fp32 -> (hi, lo) fp16
// ---------------------------------------------------------------------------
__global__ void split_kernel(const float* __restrict__ src,
                             __half* __restrict__ hi,
                             __half* __restrict__ lo, int n4) {
    int i = blockIdx.x * blockDim.x + threadIdx.x;
    if (i >= n4) return;
    float4 v = reinterpret_cast<const float4*>(src)[i];
    __half h0 = __float2half_rn(v.x), h1 = __float2half_rn(v.y);
    __half h2 = __float2half_rn(v.z), h3 = __float2half_rn(v.w);
    __half l0 = __float2half_rn(v.x - __half2float(h0));
    __half l1 = __float2half_rn(v.y - __half2float(h1));
    __half l2 = __float2half_rn(v.z - __half2float(h2));
    __half l3 = __float2half_rn(v.w - __half2float(h3));
    __half2 H01; H01.x = h0; H01.y = h1;
    __half2 H23; H23.x = h2; H23.y = h3;
    __half2 L01; L01.x = l0; L01.y = l1;
    __half2 L23; L23.x = l2; L23.y = l3;
    reinterpret_cast<__half2*>(hi)[2 * i]     = H01;
    reinterpret_cast<__half2*>(hi)[2 * i + 1] = H23;
    reinterpret_cast<__half2*>(lo)[2 * i]     = L01;
    reinterpret_cast<__half2*>(lo)[2 * i + 1] = L23;
}

// ---------------------------------------------------------------------------
// Pack + split the four projection weight matrices into g_Whi/g_Wlo + g_bcat
// ---------------------------------------------------------------------------
__global__ void pack_split_kernel(const float* __restrict__ W_B, const float* __restrict__ b_B,
                                  const float* __restrict__ W_X, const float* __restrict__ b_X,
                                  const float* __restrict__ W_d, const float* __restrict__ b_d,
                                  const float* __restrict__ W_t, const float* __restrict__ b_t) {
    int idx = blockIdx.x * blockDim.x + threadIdx.x;
    const int total = NFP * D_IN;
    for (int i = idx; i < total; i += gridDim.x * blockDim.x) {
        int f = i >> 10, k = i & 1023;
        float v = 0.f;
        if      (f < 256) v = W_B[f * D_IN + k];
        else if (f < 260) v = W_X[(f - 256) * D_IN + k];
        else if (f < 324) v = W_d[(f - 260) * D_IN + k];
        else if (f < 356) v = W_t[(f - 324) * D_IN + k];
        __half h = __float2half_rn(v);
        g_Whi[i] = h;
        g_Wlo[i] = __float2half_rn(v - __half2float(h));
    }
    if (idx < NFP) {
        float v = 0.f;
        if      (idx < 256) v = b_B[idx];
        else if (idx < 260) v = b_X[idx - 256];
        else if (idx < 324) v = b_d[idx - 260];
        else if (idx < 356) v = b_t[idx - 324];
        g_bcat[idx] = v;
    }
}

// ---------------------------------------------------------------------------
// HMMA split-fp16 GEMM: C[m][n] = sum_k A[m,k]*B[n,k]
// 2-term: A*Bhi + A*Blo (A single fp16; B = Bhi+Blo fp16 split).
// Tile 128x128, BK=32, 512 threads; warp grid 4(M) x 4(N), warp tile 32x32.
// 3-stage cp.async ring (3 tiles/stage); rows padded to 80 B.
// ---------------------------------------------------------------------------
#define ROWB 80                       // padded row stride in bytes (40 fp16)
#define TILEB (128 * ROWB)            // 10240 bytes per tile
#define STAGEB (3 * TILEB)            // A, Bhi, Blo = 30720 bytes
#define NSTAGE 3

template<bool SILU>
__global__ __launch_bounds__(512, 1)
void mma_gemm(const __half* __restrict__ A,
              const __half* __restrict__ Bhi, const __half* __restrict__ Blo,
              const float* __restrict__ bias, float* __restrict__ C, int K, int ldc) {
    extern __shared__ __align__(128) char smem[];
    const uint32_t sb = smem_u32(smem);

    const int tid = threadIdx.x;
    const int wid = tid >> 5, lane = tid & 31;
    const int wm = wid & 3;            // 0..3  (M)
    const int wn = wid >> 2;           // 0..3  (N)
    const int m0 = blockIdx.x * 128, n0 = blockIdx.y * 128;

    // cp.async: 512 chunks of 16B per tile per stage; 1 chunk/thread/tile
    const int cr = tid >> 2, ck = tid & 3;

    // ldmatrix lane addressing
    const int a_row = (lane & 7) + ((lane >> 3) & 1) * 8;   // 0..15
    const int a_kc  = lane >> 4;                            // 0..1
    const uint32_t a_base = (uint32_t)((wm * 32 + a_row) * ROWB + a_kc * 16);
    // packed-B x4: mats {j,k0},{j,k8},{j+1,k0},{j+1,k8}
    const int b_prow = (lane & 7) + ((lane >> 4) << 3);     // 0..15
    const int b_kc2  = (lane >> 3) & 1;
    const uint32_t b_base = (uint32_t)((wn * 32 + b_prow) * ROWB + b_kc2 * 16);

    float acc[2][4][4];
    #pragma unroll
    for (int i = 0; i < 2; i++)
        #pragma unroll
        for (int j = 0; j < 4; j++)
            #pragma unroll
            for (int q = 0; q < 4; q++) acc[i][j][q] = 0.f;

    const int nkb = K >> 5;

    auto load_stage = [&](int kb, int stage) {
        const uint32_t s0 = sb + stage * STAGEB;
        const int kofs = kb << 5;
        size_t ga = (size_t)(m0 + cr) * K + kofs + ck * 8;
        size_t gb = (size_t)(n0 + cr) * K + kofs + ck * 8;
        uint32_t so = (uint32_t)(cr * ROWB + ck * 16);
        CP_ASYNC16(s0 + 0 * TILEB + so, A   + ga);
        CP_ASYNC16(s0 + 1 * TILEB + so, Bhi + gb);
        CP_ASYNC16(s0 + 2 * TILEB + so, Blo + gb);
    };

    // Prologue: 2 stages in flight
    load_stage(0, 0); CP_COMMIT();
    if (nkb > 1) { load_stage(1, 1); CP_COMMIT(); }

    int stage = 0;
    for (int kb = 0; kb < nkb; kb++) {
        if (kb == nkb - 1) { CP_WAIT0(); } else { CP_WAIT1(); }
        __syncthreads();
        if (kb + 2 < nkb) {
            int ns = stage + 2; if (ns >= NSTAGE) ns -= NSTAGE;
            load_stage(kb + 2, ns);
            CP_COMMIT();
        }

        const uint32_t s0 = sb + stage * STAGEB;
        #pragma unroll
        for (int s = 0; s < 2; s++) {          // two k16 steps per BK=32
            uint32_t ah[2][4], bh[4][2], bl[4][2];
            #pragma unroll
            for (int i = 0; i < 2; i++) {
                uint32_t ao = s0 + a_base + (uint32_t)(i * 16 * ROWB + s * 32);
                ldm_x4(ah[i], ao);
            }
            #pragma unroll
            for (int jj = 0; jj < 4; jj += 2) {
                uint32_t bo = s0 + 1 * TILEB + b_base + (uint32_t)(jj * 8 * ROWB + s * 32);
                uint32_t t4[4];
                ldm_x4(t4, bo);
                bh[jj][0] = t4[0]; bh[jj][1] = t4[1];
                bh[jj + 1][0] = t4[2]; bh[jj + 1][1] = t4[3];
                ldm_x4(t4, bo + TILEB);
                bl[jj][0] = t4[0]; bl[jj][1] = t4[1];
                bl[jj + 1][0] = t4[2]; bl[jj + 1][1] = t4[3];
            }
            // pass-outer: 8 independent MMAs between accumulator RAW reuses
            #pragma unroll
            for (int i = 0; i < 2; i++)
                #pragma unroll
                for (int j = 0; j < 4; j++)
                    mma16816(acc[i][j], ah[i], bh[j]);
            #pragma unroll
            for (int i = 0; i < 2; i++)
                #pragma unroll
                for (int j = 0; j < 4; j++)
                    mma16816(acc[i][j], ah[i], bl[j]);
        }
        stage++; if (stage >= NSTAGE) stage = 0;
    }

    // Epilogue
    const int tr = lane >> 2;            // 0..7
    const int tc = (lane & 3) * 2;       // 0,2,4,6
    #pragma unroll
    for (int i = 0; i < 2; i++) {
        #pragma unroll
        for (int j = 0; j < 4; j++) {
            int m = m0 + wm * 32 + i * 16 + tr;
            int n = n0 + wn * 32 + j * 8 + tc;
            float e0 = acc[i][j][0], e1 = acc[i][j][1];
            float e2 = acc[i][j][2], e3 = acc[i][j][3];
            if (SILU) {
                float bb0 = bias[n], bb1 = bias[n + 1];
                e0 += bb0; e1 += bb1; e2 += bb0; e3 += bb1;
                e0 = e0 / (1.f + __expf(-e0));
                e1 = e1 / (1.f + __expf(-e1));
                e2 = e2 / (1.f + __expf(-e2));
                e3 = e3 / (1.f + __expf(-e3));
            }
            float2* p0 = reinterpret_cast<float2*>(C + (size_t)m * ldc + n);
            float2* p1 = reinterpret_cast<float2*>(C + (size_t)(m + 8) * ldc + n);
            *p0 = make_float2(e0, e1);
            *p1 = make_float2(e2, e3);
        }
    }
}

// ---------------------------------------------------------------------------
// Elementwise: silu/sigmoid/rotary/decay*H -> H_new (fp32) + F (fp16 single)
// ---------------------------------------------------------------------------
__global__ __launch_bounds__(256)
void elementwise_kernel(const float* __restrict__ H, const int* __restrict__ layer_idx,
                        float* __restrict__ Hnew, __half* __restrict__ Fh) {
    const int token = blockIdx.x;
    const int b = token >> 12;
    const int l = token & 4095;
    const int t = threadIdx.x;

    __shared__ float sP[NF];
    __shared__ float sB[NRF];

    for (int i = t; i < NF; i += 256)
        sP[i] = g_P[(size_t)token * NFP + i] + g_bcat[i];
    __syncthreads();

    {
        float v = sP[t];
        sB[t] = v / (1.f + __expf(-v));
    }
    __syncthreads();

    const int r = t >> 6;
    const int n = t & 63;
    const int j = n >> 1;

    const float scale = (float)(*layer_idx + 1);
    const float th = sP[324 + j] * scale;
    float cs, sn;
    sincosf(th, &sn, &cs);

    const float x1 = sB[(n & ~1) * RR + r];
    const float x2 = sB[(n |  1) * RR + r];
    const float rot = (n & 1) ? (x1 * sn + x2 * cs) : (x1 * cs - x2 * sn);

    float xv = sP[256 + r];
    const float Xr = xv / (1.f + __expf(-xv));

    float dv = sP[260 + n];
    const float decay = 1.f / (1.f + __expf(-dv));

    const size_t hidx = (((size_t)(b * RR + r) * LL + l) * NN) + n;
    const float hnew = decay * H[hidx] + rot * Xr;

    Hnew[hidx] = hnew;
    Fh[(size_t)token * NRF + (r * NN + n)] = __float2half_rn(hnew);
}

// ---------------------------------------------------------------------------
extern "C" void kernel_launch(void* const* d_in, const int* in_sizes, int n_in,
                              void* d_out, int out_size) {
    const float* x     = (const float*)d_in[0];
    const float* H     = (const float*)d_in[1];
    const float* W_B   = (const float*)d_in[2];
    const float* b_B   = (const float*)d_in[3];
    const float* W_X   = (const float*)d_in[4];
    const float* b_X   = (const float*)d_in[5];
    const float* W_d   = (const float*)d_in[6];
    const float* b_d   = (const float*)d_in[7];
    const float* W_t   = (const float*)d_in[8];
    const float* b_t   = (const float*)d_in[9];
    const float* W_out = (const float*)d_in[10];
    const float* b_out = (const float*)d_in[11];
    const int*   lidx  = (const int*)d_in[12];

    const size_t HE = (size_t)BBATCH * RR * LL * NN;   //  4,194,304
    const size_t OE = (size_t)BBATCH * LL * D_IN;      // 16,777,216

    float* hnew_dst;
    float* out_dst;
    if ((size_t)out_size >= HE + OE) {
        hnew_dst = (float*)d_out;
        out_dst  = (float*)d_out + HE;
    } else {
        cudaGetSymbolAddress((void**)&hnew_dst, g_Hscratch);
        out_dst  = (float*)d_out;
    }

    __half *xh, *Whi, *Wlo, *Fh, *Wohi, *Wolo;
    float* P_ptr;
    cudaGetSymbolAddress((void**)&xh,   g_xh);
    cudaGetSymbolAddress((void**)&Whi,  g_Whi);
    cudaGetSymbolAddress((void**)&Wlo,  g_Wlo);
    cudaGetSymbolAddress((void**)&Fh,   g_Fh);
    cudaGetSymbolAddress((void**)&Wohi, g_Wohi);
    cudaGetSymbolAddress((void**)&Wolo, g_Wolo);
    cudaGetSymbolAddress((void**)&P_ptr, g_P);

    const int SMEM_BYTES = NSTAGE * STAGEB;  // 92160
    cudaFuncSetAttribute(mma_gemm<false>, cudaFuncAttributeMaxDynamicSharedMemorySize, SMEM_BYTES);
    cudaFuncSetAttribute(mma_gemm<true>,  cudaFuncAttributeMaxDynamicSharedMemorySize, SMEM_BYTES);

    // 1) conversions / packing
    {
        int n4 = M_TOK * D_IN / 4;
        conv_half_kernel<<<(n4 + 255) / 256, 256>>>(x, xh, n4);
    }
    pack_split_kernel<<<768, 512>>>(W_B, b_B, W_X, b_X, W_d, b_d, W_t, b_t);
    {
        int n4 = D_IN * NRF / 4;
        split_kernel<<<(n4 + 255) / 256, 256>>>(W_out, Wohi, Wolo, n4);
    }

    // 2) projection GEMM: P[16384 x 384] = x @ Wcat^T  (2-pass split-fp16)
    mma_gemm<false><<<dim3(M_TOK / 128, NFP / 128), 512, SMEM_BYTES>>>(
        xh, Whi, Wlo, nullptr, P_ptr, D_IN, NFP);

    // 3) elementwise -> H_new + F (fp16)
    elementwise_kernel<<<M_TOK, 256>>>(H, lidx, hnew_dst, Fh);

    // 4) output GEMM: out[16384 x 1024] = silu(F @ W_out^T + b_out)
    mma_gemm<true><<<dim3(M_TOK / 128, D_IN / 128), 512, SMEM_BYTES>>>(
        Fh, Wohi, Wolo, b_out, out_dst, NRF, D_IN);
}

// round 15
// speedup vs baseline: 1.5147x; 1.1319x over previous
#include <cuda_runtime.h>
#include <cuda_fp16.h>
#include <math.h>
#include <stdint.h>

// Problem constants
#define M_TOK 16384      // BATCH * L
#define D_IN  1024
#define NF    356        // 256 (B) + 4 (X) + 64 (decay) + 32 (theta)
#define NFP   384        // padded feature count
#define NRF   256        // N * R
#define NN    64
#define RR    4
#define LL    4096
#define BBATCH 4

// ---------------------------------------------------------------------------
// Scratch (device globals: no runtime allocation allowed)
// ---------------------------------------------------------------------------
__device__ __half g_xh [(size_t)M_TOK * D_IN];    // x, single fp16
__device__ __half g_Whi[(size_t)NFP * D_IN];      // packed weights hi
__device__ __half g_Wlo[(size_t)NFP * D_IN];      // packed weights lo
__device__ __half g_Fh [(size_t)M_TOK * NRF];     // H_new flat, single fp16
__device__ __half g_Woh[(size_t)D_IN * NRF];      // W_out, single fp16
__device__ float g_P[(size_t)M_TOK * NFP];
__device__ float g_bcat[NFP];
__device__ float g_Hscratch[(size_t)BBATCH * RR * LL * NN];

// ---------------------------------------------------------------------------
// PTX helpers (base sm_103 target: mma.sync + ldmatrix + cp.async only)
// ---------------------------------------------------------------------------
__device__ __forceinline__ uint32_t smem_u32(const void* p) {
    uint32_t a;
    asm("{ .reg .u64 t; cvta.to.shared.u64 t, %1; cvt.u32.u64 %0, t; }" : "=r"(a) : "l"(p));
    return a;
}

#define CP_ASYNC16(saddr, gptr) \
    asm volatile("cp.async.cg.shared.global [%0], [%1], 16;" :: "r"(saddr), "l"(gptr) : "memory")
#define CP_COMMIT() asm volatile("cp.async.commit_group;" ::: "memory")
#define CP_WAIT1()  asm volatile("cp.async.wait_group 1;" ::: "memory")
#define CP_WAIT0()  asm volatile("cp.async.wait_group 0;" ::: "memory")

__device__ __forceinline__ void ldm_x4(uint32_t* r, uint32_t addr) {
    asm volatile("ldmatrix.sync.aligned.m8n8.x4.shared.b16 {%0,%1,%2,%3}, [%4];"
                 : "=r"(r[0]), "=r"(r[1]), "=r"(r[2]), "=r"(r[3]) : "r"(addr));
}
__device__ __forceinline__ void mma16816(float* c, const uint32_t* a, const uint32_t* b) {
    asm volatile(
        "mma.sync.aligned.m16n8k16.row.col.f32.f16.f16.f32 "
        "{%0,%1,%2,%3}, {%4,%5,%6,%7}, {%8,%9}, {%0,%1,%2,%3};"
        : "+f"(c[0]), "+f"(c[1]), "+f"(c[2]), "+f"(c[3])
        : "r"(a[0]), "r"(a[1]), "r"(a[2]), "r"(a[3]), "r"(b[0]), "r"(b[1]));
}

// ---------------------------------------------------------------------------
// Convert fp32 -> fp16 (single plane)
// ---------------------------------------------------------------------------
__global__ void conv_half_kernel(const float* __restrict__ src,
                                 __half* __restrict__ dst, int n4) {
    int i = blockIdx.x * blockDim.x + threadIdx.x;
    if (i >= n4) return;
    float4 v = reinterpret_cast<const float4*>(src)[i];
    __half2 a = __floats2half2_rn(v.x, v.y);
    __half2 b = __floats2half2_rn(v.z, v.w);
    reinterpret_cast<__half2*>(dst)[2 * i]     = a;
    reinterpret_cast<__half2*>(dst)[2 * i + 1] = b;
}

// ---------------------------------------------------------------------------
// Pack + split the four projection weight matrices into g_Whi/g_Wlo + g_bcat
// ---------------------------------------------------------------------------
__global__ void pack_split_kernel(const float* __restrict__ W_B, const float* __restrict__ b_B,
                                  const float* __restrict__ W_X, const float* __restrict__ b_X,
                                  const float* __restrict__ W_d, const float* __restrict__ b_d,
                                  const float* __restrict__ W_t, const float* __restrict__ b_t) {
    int idx = blockIdx.x * blockDim.x + threadIdx.x;
    const int total = NFP * D_IN;
    for (int i = idx; i < total; i += gridDim.x * blockDim.x) {
        int f = i >> 10, k = i & 1023;
        float v = 0.f;
        if      (f < 256) v = W_B[f * D_IN + k];
        else if (f < 260) v = W_X[(f - 256) * D_IN + k];
        else if (f < 324) v = W_d[(f - 260) * D_IN + k];
        else if (f < 356) v = W_t[(f - 324) * D_IN + k];
        __half h = __float2half_rn(v);
        g_Whi[i] = h;
        g_Wlo[i] = __float2half_rn(v - __half2float(h));
    }
    if (idx < NFP) {
        float v = 0.f;
        if      (idx < 256) v = b_B[idx];
        else if (idx < 260) v = b_X[idx - 256];
        else if (idx < 324) v = b_d[idx - 260];
        else if (idx < 356) v = b_t[idx - 324];
        g_bcat[idx] = v;
    }
}

// ---------------------------------------------------------------------------
// HMMA fp16 GEMM: C[m][n] = sum_k A[m,k]*B[n,k]
// PASSES==2: B = Bhi+Blo split (2 MMA passes). PASSES==1: single Bhi pass.
// Tile 128x128, BK=32, 512 threads; warp grid 4(M) x 4(N), warp tile 32x32.
// 3-stage cp.async ring; rows padded to 80 B -> ldmatrix conflict-free.
// ---------------------------------------------------------------------------
#define ROWB 80                       // padded row stride in bytes (40 fp16)
#define TILEB (128 * ROWB)            // 10240 bytes per tile
#define NSTAGE 3

template<bool SILU, int PASSES>
__global__ __launch_bounds__(512, 1)
void mma_gemm(const __half* __restrict__ A,
              const __half* __restrict__ Bhi, const __half* __restrict__ Blo,
              const float* __restrict__ bias, float* __restrict__ C, int K, int ldc) {
    constexpr int NTILES = (PASSES == 2) ? 3 : 2;       // A, Bhi[, Blo]
    constexpr int STAGEB = NTILES * TILEB;
    extern __shared__ __align__(128) char smem[];
    const uint32_t sb = smem_u32(smem);

    const int tid = threadIdx.x;
    const int wid = tid >> 5, lane = tid & 31;
    const int wm = wid & 3;            // 0..3  (M)
    const int wn = wid >> 2;           // 0..3  (N)
    const int m0 = blockIdx.x * 128, n0 = blockIdx.y * 128;

    // cp.async: 512 chunks of 16B per tile per stage; 1 chunk/thread/tile
    const int cr = tid >> 2, ck = tid & 3;

    // ldmatrix lane addressing
    const int a_row = (lane & 7) + ((lane >> 3) & 1) * 8;   // 0..15
    const int a_kc  = lane >> 4;                            // 0..1
    const uint32_t a_base = (uint32_t)((wm * 32 + a_row) * ROWB + a_kc * 16);
    // packed-B x4: mats {j,k0},{j,k8},{j+1,k0},{j+1,k8}
    const int b_prow = (lane & 7) + ((lane >> 4) << 3);     // 0..15
    const int b_kc2  = (lane >> 3) & 1;
    const uint32_t b_base = (uint32_t)((wn * 32 + b_prow) * ROWB + b_kc2 * 16);

    float acc[2][4][4];
    #pragma unroll
    for (int i = 0; i < 2; i++)
        #pragma unroll
        for (int j = 0; j < 4; j++)
            #pragma unroll
            for (int q = 0; q < 4; q++) acc[i][j][q] = 0.f;

    const int nkb = K >> 5;

    auto load_stage = [&](int kb, int stage) {
        const uint32_t s0 = sb + stage * STAGEB;
        const int kofs = kb << 5;
        size_t ga = (size_t)(m0 + cr) * K + kofs + ck * 8;
        size_t gb = (size_t)(n0 + cr) * K + kofs + ck * 8;
        uint32_t so = (uint32_t)(cr * ROWB + ck * 16);
        CP_ASYNC16(s0 + 0 * TILEB + so, A   + ga);
        CP_ASYNC16(s0 + 1 * TILEB + so, Bhi + gb);
        if (PASSES == 2) CP_ASYNC16(s0 + 2 * TILEB + so, Blo + gb);
    };

    // Prologue: 2 stages in flight
    load_stage(0, 0); CP_COMMIT();
    if (nkb > 1) { load_stage(1, 1); CP_COMMIT(); }

    int stage = 0;
    for (int kb = 0; kb < nkb; kb++) {
        if (kb == nkb - 1) { CP_WAIT0(); } else { CP_WAIT1(); }
        __syncthreads();
        if (kb + 2 < nkb) {
            int ns = stage + 2; if (ns >= NSTAGE) ns -= NSTAGE;
            load_stage(kb + 2, ns);
            CP_COMMIT();
        }

        const uint32_t s0 = sb + stage * STAGEB;
        #pragma unroll
        for (int s = 0; s < 2; s++) {          // two k16 steps per BK=32
            uint32_t ah[2][4], bh[4][2];
            #pragma unroll
            for (int i = 0; i < 2; i++) {
                uint32_t ao = s0 + a_base + (uint32_t)(i * 16 * ROWB + s * 32);
                ldm_x4(ah[i], ao);
            }
            #pragma unroll
            for (int jj = 0; jj < 4; jj += 2) {
                uint32_t bo = s0 + 1 * TILEB + b_base + (uint32_t)(jj * 8 * ROWB + s * 32);
                uint32_t t4[4];
                ldm_x4(t4, bo);
                bh[jj][0] = t4[0]; bh[jj][1] = t4[1];
                bh[jj + 1][0] = t4[2]; bh[jj + 1][1] = t4[3];
            }
            #pragma unroll
            for (int i = 0; i < 2; i++)
                #pragma unroll
                for (int j = 0; j < 4; j++)
                    mma16816(acc[i][j], ah[i], bh[j]);
            if (PASSES == 2) {
                uint32_t bl[4][2];
                #pragma unroll
                for (int jj = 0; jj < 4; jj += 2) {
                    uint32_t bo = s0 + 2 * TILEB + b_base + (uint32_t)(jj * 8 * ROWB + s * 32);
                    uint32_t t4[4];
                    ldm_x4(t4, bo);
                    bl[jj][0] = t4[0]; bl[jj][1] = t4[1];
                    bl[jj + 1][0] = t4[2]; bl[jj + 1][1] = t4[3];
                }
                #pragma unroll
                for (int i = 0; i < 2; i++)
                    #pragma unroll
                    for (int j = 0; j < 4; j++)
                        mma16816(acc[i][j], ah[i], bl[j]);
            }
        }
        stage++; if (stage >= NSTAGE) stage = 0;
    }

    // Epilogue
    const int tr = lane >> 2;            // 0..7
    const int tc = (lane & 3) * 2;       // 0,2,4,6
    #pragma unroll
    for (int i = 0; i < 2; i++) {
        #pragma unroll
        for (int j = 0; j < 4; j++) {
            int m = m0 + wm * 32 + i * 16 + tr;
            int n = n0 + wn * 32 + j * 8 + tc;
            float e0 = acc[i][j][0], e1 = acc[i][j][1];
            float e2 = acc[i][j][2], e3 = acc[i][j][3];
            if (SILU) {
                float bb0 = bias[n], bb1 = bias[n + 1];
                e0 += bb0; e1 += bb1; e2 += bb0; e3 += bb1;
                e0 = __fdividef(e0, 1.f + __expf(-e0));
                e1 = __fdividef(e1, 1.f + __expf(-e1));
                e2 = __fdividef(e2, 1.f + __expf(-e2));
                e3 = __fdividef(e3, 1.f + __expf(-e3));
            }
            float2* p0 = reinterpret_cast<float2*>(C + (size_t)m * ldc + n);
            float2* p1 = reinterpret_cast<float2*>(C + (size_t)(m + 8) * ldc + n);
            *p0 = make_float2(e0, e1);
            *p1 = make_float2(e2, e3);
        }
    }
}

// ---------------------------------------------------------------------------
// Elementwise: silu/sigmoid/rotary/decay*H -> H_new (fp32) + F (fp16 single)
// De-duplicated transcendentals: stage silu(B) [256], sincos [32], decay [64],
// silu(X) [4] once per token, then combine. Fast intrinsics throughout.
// ---------------------------------------------------------------------------
__global__ __launch_bounds__(256)
void elementwise_kernel(const float* __restrict__ H, const int* __restrict__ layer_idx,
                        float* __restrict__ Hnew, __half* __restrict__ Fh) {
    const int token = blockIdx.x;
    const int b = token >> 12;
    const int l = token & 4095;
    const int t = threadIdx.x;

    __shared__ float sP[NF];
    __shared__ float sB[NRF];
    __shared__ float sD[NN];
    __shared__ float sC[NN / 2];
    __shared__ float sS[NN / 2];
    __shared__ float sX[RR];

    for (int i = t; i < NF; i += 256)
        sP[i] = g_P[(size_t)token * NFP + i] + g_bcat[i];
    __syncthreads();

    {   // silu of the 256 B-projection features
        float v = sP[t];
        sB[t] = __fdividef(v, 1.f + __expf(-v));
    }
    if (t < NN) {                       // decay sigmoid (64 distinct)
        float dv = sP[260 + t];
        sD[t] = __fdividef(1.f, 1.f + __expf(-dv));
    }
    if (t < NN / 2) {                   // rotary sincos (32 distinct)
        const float scale = (float)(*layer_idx + 1);
        float th = sP[324 + t] * scale;
        float cs, sn;
        __sincosf(th, &sn, &cs);
        sC[t] = cs; sS[t] = sn;
    }
    if (t < RR) {                       // X_r silu (4 distinct)
        float xv = sP[256 + t];
        sX[t] = __fdividef(xv, 1.f + __expf(-xv));
    }
    __syncthreads();

    const int r = t >> 6;
    const int n = t & 63;
    const int j = n >> 1;

    const float x1 = sB[(n & ~1) * RR + r];
    const float x2 = sB[(n |  1) * RR + r];
    const float rot = (n & 1) ? (x1 * sS[j] + x2 * sC[j]) : (x1 * sC[j] - x2 * sS[j]);

    const size_t hidx = (((size_t)(b * RR + r) * LL + l) * NN) + n;
    const float hnew = sD[n] * H[hidx] + rot * sX[r];

    Hnew[hidx] = hnew;
    Fh[(size_t)token * NRF + (r * NN + n)] = __float2half_rn(hnew);
}

// ---------------------------------------------------------------------------
extern "C" void kernel_launch(void* const* d_in, const int* in_sizes, int n_in,
                              void* d_out, int out_size) {
    const float* x     = (const float*)d_in[0];
    const float* H     = (const float*)d_in[1];
    const float* W_B   = (const float*)d_in[2];
    const float* b_B   = (const float*)d_in[3];
    const float* W_X   = (const float*)d_in[4];
    const float* b_X   = (const float*)d_in[5];
    const float* W_d   = (const float*)d_in[6];
    const float* b_d   = (const float*)d_in[7];
    const float* W_t   = (const float*)d_in[8];
    const float* b_t   = (const float*)d_in[9];
    const float* W_out = (const float*)d_in[10];
    const float* b_out = (const float*)d_in[11];
    const int*   lidx  = (const int*)d_in[12];

    const size_t HE = (size_t)BBATCH * RR * LL * NN;   //  4,194,304
    const size_t OE = (size_t)BBATCH * LL * D_IN;      // 16,777,216

    float* hnew_dst;
    float* out_dst;
    if ((size_t)out_size >= HE + OE) {
        hnew_dst = (float*)d_out;
        out_dst  = (float*)d_out + HE;
    } else {
        cudaGetSymbolAddress((void**)&hnew_dst, g_Hscratch);
        out_dst  = (float*)d_out;
    }

    __half *xh, *Whi, *Wlo, *Fh, *Woh;
    float* P_ptr;
    cudaGetSymbolAddress((void**)&xh,   g_xh);
    cudaGetSymbolAddress((void**)&Whi,  g_Whi);
    cudaGetSymbolAddress((void**)&Wlo,  g_Wlo);
    cudaGetSymbolAddress((void**)&Fh,   g_Fh);
    cudaGetSymbolAddress((void**)&Woh,  g_Woh);
    cudaGetSymbolAddress((void**)&P_ptr, g_P);

    const int SMEM_G1 = NSTAGE * 3 * TILEB;  // 92160 (2-pass: A,Bhi,Blo)
    const int SMEM_G2 = NSTAGE * 2 * TILEB;  // 61440 (1-pass: A,Bhi)
    cudaFuncSetAttribute((const void*)mma_gemm<false, 2>,
                         cudaFuncAttributeMaxDynamicSharedMemorySize, SMEM_G1);
    cudaFuncSetAttribute((const void*)mma_gemm<true, 1>,
                         cudaFuncAttributeMaxDynamicSharedMemorySize, SMEM_G2);

    // 1) conversions / packing
    {
        int n4 = M_TOK * D_IN / 4;
        conv_half_kernel<<<(n4 + 255) / 256, 256>>>(x, xh, n4);
    }
    pack_split_kernel<<<768, 512>>>(W_B, b_B, W_X, b_X, W_d, b_d, W_t, b_t);
    {
        int n4 = D_IN * NRF / 4;
        conv_half_kernel<<<(n4 + 255) / 256, 256>>>(W_out, Woh, n4);
    }

    // 2) projection GEMM: P[16384 x 384] = x @ Wcat^T  (2-pass split-fp16)
    mma_gemm<false, 2><<<dim3(M_TOK / 128, NFP / 128), 512, SMEM_G1>>>(
        xh, Whi, Wlo, nullptr, P_ptr, D_IN, NFP);

    // 3) elementwise -> H_new + F (fp16)
    elementwise_kernel<<<M_TOK, 256>>>(H, lidx, hnew_dst, Fh);

    // 4) output GEMM: out[16384 x 1024] = silu(F @ W_out^T + b_out)  (1-pass)
    mma_gemm<true, 1><<<dim3(M_TOK / 128, D_IN / 128), 512, SMEM_G2>>>(
        Fh, Woh, nullptr, b_out, out_dst, NRF, D_IN);
}

// round 16
// speedup vs baseline: 1.7171x; 1.1336x over previous
#include <cuda_runtime.h>
#include <cuda_fp16.h>
#include <math.h>
#include <stdint.h>

// Problem constants
#define M_TOK 16384      // BATCH * L
#define D_IN  1024
#define NF    356        // 256 (B) + 4 (X) + 64 (decay) + 32 (theta)
#define NFP   384        // padded feature count
#define NRF   256        // N * R
#define NN    64
#define RR    4
#define LL    4096
#define BBATCH 4

// ---------------------------------------------------------------------------
// Scratch (device globals: no runtime allocation allowed)
// ---------------------------------------------------------------------------
__device__ __half g_xh [(size_t)M_TOK * D_IN];    // x, single fp16
__device__ __half g_Whi[(size_t)NFP * D_IN];      // packed weights hi
__device__ __half g_Wlo[(size_t)NFP * D_IN];      // packed weights lo
__device__ __half g_Fh [(size_t)M_TOK * NRF];     // H_new flat, single fp16
__device__ __half g_Woh[(size_t)D_IN * NRF];      // W_out, single fp16
__device__ float g_P[(size_t)M_TOK * NFP];
__device__ float g_bcat[NFP];
__device__ float g_Hscratch[(size_t)BBATCH * RR * LL * NN];

// ---------------------------------------------------------------------------
// PTX helpers (base sm_103 target: mma.sync + ldmatrix + cp.async only)
// ---------------------------------------------------------------------------
__device__ __forceinline__ uint32_t smem_u32(const void* p) {
    uint32_t a;
    asm("{ .reg .u64 t; cvta.to.shared.u64 t, %1; cvt.u32.u64 %0, t; }" : "=r"(a) : "l"(p));
    return a;
}

#define CP_ASYNC16(saddr, gptr) \
    asm volatile("cp.async.cg.shared.global [%0], [%1], 16;" :: "r"(saddr), "l"(gptr) : "memory")
#define CP_COMMIT() asm volatile("cp.async.commit_group;" ::: "memory")
#define CP_WAIT1()  asm volatile("cp.async.wait_group 1;" ::: "memory")
#define CP_WAIT0()  asm volatile("cp.async.wait_group 0;" ::: "memory")

__device__ __forceinline__ void ldm_x4(uint32_t* r, uint32_t addr) {
    asm volatile("ldmatrix.sync.aligned.m8n8.x4.shared.b16 {%0,%1,%2,%3}, [%4];"
                 : "=r"(r[0]), "=r"(r[1]), "=r"(r[2]), "=r"(r[3]) : "r"(addr));
}
__device__ __forceinline__ void mma16816(float* c, const uint32_t* a, const uint32_t* b) {
    asm volatile(
        "mma.sync.aligned.m16n8k16.row.col.f32.f16.f16.f32 "
        "{%0,%1,%2,%3}, {%4,%5,%6,%7}, {%8,%9}, {%0,%1,%2,%3};"
        : "+f"(c[0]), "+f"(c[1]), "+f"(c[2]), "+f"(c[3])
        : "r"(a[0]), "r"(a[1]), "r"(a[2]), "r"(a[3]), "r"(b[0]), "r"(b[1]));
}

// ---------------------------------------------------------------------------
// Convert fp32 -> fp16 (single plane)
// ---------------------------------------------------------------------------
__global__ void conv_half_kernel(const float* __restrict__ src,
                                 __half* __restrict__ dst, int n4) {
    int i = blockIdx.x * blockDim.x + threadIdx.x;
    if (i >= n4) return;
    float4 v = reinterpret_cast<const float4*>(src)[i];
    __half2 a = __floats2half2_rn(v.x, v.y);
    __half2 b = __floats2half2_rn(v.z, v.w);
    reinterpret_cast<__half2*>(dst)[2 * i]     = a;
    reinterpret_cast<__half2*>(dst)[2 * i + 1] = b;
}

// ---------------------------------------------------------------------------
// Pack + split the four projection weight matrices into g_Whi/g_Wlo + g_bcat
// ---------------------------------------------------------------------------
__global__ void pack_split_kernel(const float* __restrict__ W_B, const float* __restrict__ b_B,
                                  const float* __restrict__ W_X, const float* __restrict__ b_X,
                                  const float* __restrict__ W_d, const float* __restrict__ b_d,
                                  const float* __restrict__ W_t, const float* __restrict__ b_t) {
    int idx = blockIdx.x * blockDim.x + threadIdx.x;
    const int total = NFP * D_IN;
    for (int i = idx; i < total; i += gridDim.x * blockDim.x) {
        int f = i >> 10, k = i & 1023;
        float v = 0.f;
        if      (f < 256) v = W_B[f * D_IN + k];
        else if (f < 260) v = W_X[(f - 256) * D_IN + k];
        else if (f < 324) v = W_d[(f - 260) * D_IN + k];
        else if (f < 356) v = W_t[(f - 324) * D_IN + k];
        __half h = __float2half_rn(v);
        g_Whi[i] = h;
        g_Wlo[i] = __float2half_rn(v - __half2float(h));
    }
    if (idx < NFP) {
        float v = 0.f;
        if      (idx < 256) v = b_B[idx];
        else if (idx < 260) v = b_X[idx - 256];
        else if (idx < 324) v = b_d[idx - 260];
        else if (idx < 356) v = b_t[idx - 324];
        g_bcat[idx] = v;
    }
}

// ---------------------------------------------------------------------------
// HMMA fp16 GEMM: C[m][n] = sum_k A[m,k]*B[n,k]
// Per-N-block pass selection: blocks with blockIdx.y >= ny2 run the second
// (Blo) pass; others run single-pass. NTILES=3 reserves smem for Blo.
// Tile 128x128, BK=32, 512 threads; warp grid 4(M) x 4(N), warp tile 32x32.
// 3-stage cp.async ring; rows padded to 80 B -> ldmatrix conflict-free.
// ---------------------------------------------------------------------------
#define ROWB 80                       // padded row stride in bytes (40 fp16)
#define TILEB (128 * ROWB)            // 10240 bytes per tile
#define NSTAGE 3

template<bool SILU, int NTILES>
__global__ __launch_bounds__(512, 1)
void mma_gemm(const __half* __restrict__ A,
              const __half* __restrict__ Bhi, const __half* __restrict__ Blo,
              const float* __restrict__ bias, float* __restrict__ C,
              int K, int ldc, int ny2) {
    constexpr int STAGEB = NTILES * TILEB;
    extern __shared__ __align__(128) char smem[];
    const uint32_t sb = smem_u32(smem);

    const bool two_pass = (NTILES == 3) && ((int)blockIdx.y >= ny2);

    const int tid = threadIdx.x;
    const int wid = tid >> 5, lane = tid & 31;
    const int wm = wid & 3;            // 0..3  (M)
    const int wn = wid >> 2;           // 0..3  (N)
    const int m0 = blockIdx.x * 128, n0 = blockIdx.y * 128;

    // cp.async: 512 chunks of 16B per tile per stage; 1 chunk/thread/tile
    const int cr = tid >> 2, ck = tid & 3;

    // ldmatrix lane addressing
    const int a_row = (lane & 7) + ((lane >> 3) & 1) * 8;   // 0..15
    const int a_kc  = lane >> 4;                            // 0..1
    const uint32_t a_base = (uint32_t)((wm * 32 + a_row) * ROWB + a_kc * 16);
    // packed-B x4: mats {j,k0},{j,k8},{j+1,k0},{j+1,k8}
    const int b_prow = (lane & 7) + ((lane >> 4) << 3);     // 0..15
    const int b_kc2  = (lane >> 3) & 1;
    const uint32_t b_base = (uint32_t)((wn * 32 + b_prow) * ROWB + b_kc2 * 16);

    float acc[2][4][4];
    #pragma unroll
    for (int i = 0; i < 2; i++)
        #pragma unroll
        for (int j = 0; j < 4; j++)
            #pragma unroll
            for (int q = 0; q < 4; q++) acc[i][j][q] = 0.f;

    const int nkb = K >> 5;

    auto load_stage = [&](int kb, int stage) {
        const uint32_t s0 = sb + stage * STAGEB;
        const int kofs = kb << 5;
        size_t ga = (size_t)(m0 + cr) * K + kofs + ck * 8;
        size_t gb = (size_t)(n0 + cr) * K + kofs + ck * 8;
        uint32_t so = (uint32_t)(cr * ROWB + ck * 16);
        CP_ASYNC16(s0 + 0 * TILEB + so, A   + ga);
        CP_ASYNC16(s0 + 1 * TILEB + so, Bhi + gb);
        if (NTILES == 3 && two_pass) CP_ASYNC16(s0 + 2 * TILEB + so, Blo + gb);
    };

    // Prologue: 2 stages in flight
    load_stage(0, 0); CP_COMMIT();
    if (nkb > 1) { load_stage(1, 1); CP_COMMIT(); }

    int stage = 0;
    for (int kb = 0; kb < nkb; kb++) {
        if (kb == nkb - 1) { CP_WAIT0(); } else { CP_WAIT1(); }
        __syncthreads();
        if (kb + 2 < nkb) {
            int ns = stage + 2; if (ns >= NSTAGE) ns -= NSTAGE;
            load_stage(kb + 2, ns);
            CP_COMMIT();
        }

        const uint32_t s0 = sb + stage * STAGEB;
        #pragma unroll
        for (int s = 0; s < 2; s++) {          // two k16 steps per BK=32
            uint32_t ah[2][4], bh[4][2];
            #pragma unroll
            for (int i = 0; i < 2; i++) {
                uint32_t ao = s0 + a_base + (uint32_t)(i * 16 * ROWB + s * 32);
                ldm_x4(ah[i], ao);
            }
            #pragma unroll
            for (int jj = 0; jj < 4; jj += 2) {
                uint32_t bo = s0 + 1 * TILEB + b_base + (uint32_t)(jj * 8 * ROWB + s * 32);
                uint32_t t4[4];
                ldm_x4(t4, bo);
                bh[jj][0] = t4[0]; bh[jj][1] = t4[1];
                bh[jj + 1][0] = t4[2]; bh[jj + 1][1] = t4[3];
            }
            #pragma unroll
            for (int i = 0; i < 2; i++)
                #pragma unroll
                for (int j = 0; j < 4; j++)
                    mma16816(acc[i][j], ah[i], bh[j]);
            if (NTILES == 3 && two_pass) {
                uint32_t bl[4][2];
                #pragma unroll
                for (int jj = 0; jj < 4; jj += 2) {
                    uint32_t bo = s0 + 2 * TILEB + b_base + (uint32_t)(jj * 8 * ROWB + s * 32);
                    uint32_t t4[4];
                    ldm_x4(t4, bo);
                    bl[jj][0] = t4[0]; bl[jj][1] = t4[1];
                    bl[jj + 1][0] = t4[2]; bl[jj + 1][1] = t4[3];
                }
                #pragma unroll
                for (int i = 0; i < 2; i++)
                    #pragma unroll
                    for (int j = 0; j < 4; j++)
                        mma16816(acc[i][j], ah[i], bl[j]);
            }
        }
        stage++; if (stage >= NSTAGE) stage = 0;
    }

    // Epilogue
    const int tr = lane >> 2;            // 0..7
    const int tc = (lane & 3) * 2;       // 0,2,4,6
    #pragma unroll
    for (int i = 0; i < 2; i++) {
        #pragma unroll
        for (int j = 0; j < 4; j++) {
            int m = m0 + wm * 32 + i * 16 + tr;
            int n = n0 + wn * 32 + j * 8 + tc;
            float e0 = acc[i][j][0], e1 = acc[i][j][1];
            float e2 = acc[i][j][2], e3 = acc[i][j][3];
            if (SILU) {
                float bb0 = bias[n], bb1 = bias[n + 1];
                e0 += bb0; e1 += bb1; e2 += bb0; e3 += bb1;
                e0 = __fdividef(e0, 1.f + __expf(-e0));
                e1 = __fdividef(e1, 1.f + __expf(-e1));
                e2 = __fdividef(e2, 1.f + __expf(-e2));
                e3 = __fdividef(e3, 1.f + __expf(-e3));
            }
            float2* p0 = reinterpret_cast<float2*>(C + (size_t)m * ldc + n);
            float2* p1 = reinterpret_cast<float2*>(C + (size_t)(m + 8) * ldc + n);
            *p0 = make_float2(e0, e1);
            *p1 = make_float2(e2, e3);
        }
    }
}

// ---------------------------------------------------------------------------
// Elementwise: silu/sigmoid/rotary/decay*H -> H_new (fp32) + F (fp16 single)
// De-duplicated transcendentals staged in smem; fast intrinsics throughout.
// ---------------------------------------------------------------------------
__global__ __launch_bounds__(256)
void elementwise_kernel(const float* __restrict__ H, const int* __restrict__ layer_idx,
                        float* __restrict__ Hnew, __half* __restrict__ Fh) {
    const int token = blockIdx.x;
    const int b = token >> 12;
    const int l = token & 4095;
    const int t = threadIdx.x;

    __shared__ float sP[NF];
    __shared__ float sB[NRF];
    __shared__ float sD[NN];
    __shared__ float sC[NN / 2];
    __shared__ float sS[NN / 2];
    __shared__ float sX[RR];

    for (int i = t; i < NF; i += 256)
        sP[i] = g_P[(size_t)token * NFP + i] + g_bcat[i];
    __syncthreads();

    {   // silu of the 256 B-projection features
        float v = sP[t];
        sB[t] = __fdividef(v, 1.f + __expf(-v));
    }
    if (t < NN) {                       // decay sigmoid (64 distinct)
        float dv = sP[260 + t];
        sD[t] = __fdividef(1.f, 1.f + __expf(-dv));
    }
    if (t < NN / 2) {                   // rotary sincos (32 distinct)
        const float scale = (float)(*layer_idx + 1);
        float th = sP[324 + t] * scale;
        float cs, sn;
        __sincosf(th, &sn, &cs);
        sC[t] = cs; sS[t] = sn;
    }
    if (t < RR) {                       // X_r silu (4 distinct)
        float xv = sP[256 + t];
        sX[t] = __fdividef(xv, 1.f + __expf(-xv));
    }
    __syncthreads();

    const int r = t >> 6;
    const int n = t & 63;
    const int j = n >> 1;

    const float x1 = sB[(n & ~1) * RR + r];
    const float x2 = sB[(n |  1) * RR + r];
    const float rot = (n & 1) ? (x1 * sS[j] + x2 * sC[j]) : (x1 * sC[j] - x2 * sS[j]);

    const size_t hidx = (((size_t)(b * RR + r) * LL + l) * NN) + n;
    const float hnew = sD[n] * H[hidx] + rot * sX[r];

    Hnew[hidx] = hnew;
    Fh[(size_t)token * NRF + (r * NN + n)] = __float2half_rn(hnew);
}

// ---------------------------------------------------------------------------
extern "C" void kernel_launch(void* const* d_in, const int* in_sizes, int n_in,
                              void* d_out, int out_size) {
    const float* x     = (const float*)d_in[0];
    const float* H     = (const float*)d_in[1];
    const float* W_B   = (const float*)d_in[2];
    const float* b_B   = (const float*)d_in[3];
    const float* W_X   = (const float*)d_in[4];
    const float* b_X   = (const float*)d_in[5];
    const float* W_d   = (const float*)d_in[6];
    const float* b_d   = (const float*)d_in[7];
    const float* W_t   = (const float*)d_in[8];
    const float* b_t   = (const float*)d_in[9];
    const float* W_out = (const float*)d_in[10];
    const float* b_out = (const float*)d_in[11];
    const int*   lidx  = (const int*)d_in[12];

    const size_t HE = (size_t)BBATCH * RR * LL * NN;   //  4,194,304
    const size_t OE = (size_t)BBATCH * LL * D_IN;      // 16,777,216

    float* hnew_dst;
    float* out_dst;
    if ((size_t)out_size >= HE + OE) {
        hnew_dst = (float*)d_out;
        out_dst  = (float*)d_out + HE;
    } else {
        cudaGetSymbolAddress((void**)&hnew_dst, g_Hscratch);
        out_dst  = (float*)d_out;
    }

    __half *xh, *Whi, *Wlo, *Fh, *Woh;
    float* P_ptr;
    cudaGetSymbolAddress((void**)&xh,   g_xh);
    cudaGetSymbolAddress((void**)&Whi,  g_Whi);
    cudaGetSymbolAddress((void**)&Wlo,  g_Wlo);
    cudaGetSymbolAddress((void**)&Fh,   g_Fh);
    cudaGetSymbolAddress((void**)&Woh,  g_Woh);
    cudaGetSymbolAddress((void**)&P_ptr, g_P);

    const int SMEM_G1 = NSTAGE * 3 * TILEB;  // 92160 (A,Bhi,Blo)
    const int SMEM_G2 = NSTAGE * 2 * TILEB;  // 61440 (A,Bhi)
    cudaFuncSetAttribute((const void*)mma_gemm<false, 3>,
                         cudaFuncAttributeMaxDynamicSharedMemorySize, SMEM_G1);
    cudaFuncSetAttribute((const void*)mma_gemm<true, 2>,
                         cudaFuncAttributeMaxDynamicSharedMemorySize, SMEM_G2);

    // 1) conversions / packing
    {
        int n4 = M_TOK * D_IN / 4;
        conv_half_kernel<<<(n4 + 255) / 256, 256>>>(x, xh, n4);
    }
    pack_split_kernel<<<768, 512>>>(W_B, b_B, W_X, b_X, W_d, b_d, W_t, b_t);
    {
        int n4 = D_IN * NRF / 4;
        conv_half_kernel<<<(n4 + 255) / 256, 256>>>(W_out, Woh, n4);
    }

    // 2) projection GEMM: P[16384 x 384] = x @ Wcat^T
    //    N-blocks 0,1 (B_proj cols 0-255): 1-pass fp16
    //    N-block  2   (X/decay/theta cols 256-383): 2-pass split-fp16
    mma_gemm<false, 3><<<dim3(M_TOK / 128, NFP / 128), 512, SMEM_G1>>>(
        xh, Whi, Wlo, nullptr, P_ptr, D_IN, NFP, /*ny2=*/2);

    // 3) elementwise -> H_new + F (fp16)
    elementwise_kernel<<<M_TOK, 256>>>(H, lidx, hnew_dst, Fh);

    // 4) output GEMM: out[16384 x 1024] = silu(F @ W_out^T + b_out)  (1-pass)
    mma_gemm<true, 2><<<dim3(M_TOK / 128, D_IN / 128), 512, SMEM_G2>>>(
        Fh, Woh, nullptr, b_out, out_dst, NRF, D_IN, /*ny2=*/1 << 30);
}

// round 17
// speedup vs baseline: 1.8194x; 1.0596x over previous
#include <cuda_runtime.h>
#include <cuda_fp16.h>
#include <math.h>
#include <stdint.h>

// Problem constants
#define M_TOK 16384      // BATCH * L
#define D_IN  1024
#define NFP   384        // padded feature count
#define NRF   256        // N * R
#define NN    64
#define RR    4
#define LL    4096
#define BBATCH 4

// Packed projection layout (our choice):
//   cols [0,32)    = theta   (needs 2-pass: error amplified x3 into sincos)
//   cols [32,36)   = X
//   cols [36,100)  = decay
//   cols [100,128) = pad
//   cols [128,384) = B_proj
#define OFF_THETA 0
#define OFF_X     32
#define OFF_DECAY 36
#define OFF_B     128

// ---------------------------------------------------------------------------
// Scratch (device globals: no runtime allocation allowed)
// ---------------------------------------------------------------------------
__device__ __half g_xh [(size_t)M_TOK * D_IN];    // x, single fp16
__device__ __half g_Whi[(size_t)NFP * D_IN];      // packed weights hi
__device__ __half g_Wlo[(size_t)NFP * D_IN];      // packed weights lo
__device__ __half g_Fh [(size_t)M_TOK * NRF];     // H_new flat, single fp16
__device__ __half g_Woh[(size_t)D_IN * NRF];      // W_out, single fp16
__device__ float g_P[(size_t)M_TOK * NFP];
__device__ float g_bcat[NFP];
__device__ float g_Hscratch[(size_t)BBATCH * RR * LL * NN];

// ---------------------------------------------------------------------------
// PTX helpers (base sm_103 target: mma.sync + ldmatrix + cp.async only)
// ---------------------------------------------------------------------------
__device__ __forceinline__ uint32_t smem_u32(const void* p) {
    uint32_t a;
    asm("{ .reg .u64 t; cvta.to.shared.u64 t, %1; cvt.u32.u64 %0, t; }" : "=r"(a) : "l"(p));
    return a;
}

#define CP_ASYNC16(saddr, gptr) \
    asm volatile("cp.async.cg.shared.global [%0], [%1], 16;" :: "r"(saddr), "l"(gptr) : "memory")
#define CP_COMMIT() asm volatile("cp.async.commit_group;" ::: "memory")
#define CP_WAIT1()  asm volatile("cp.async.wait_group 1;" ::: "memory")
#define CP_WAIT0()  asm volatile("cp.async.wait_group 0;" ::: "memory")

__device__ __forceinline__ void ldm_x4(uint32_t* r, uint32_t addr) {
    asm volatile("ldmatrix.sync.aligned.m8n8.x4.shared.b16 {%0,%1,%2,%3}, [%4];"
                 : "=r"(r[0]), "=r"(r[1]), "=r"(r[2]), "=r"(r[3]) : "r"(addr));
}
__device__ __forceinline__ void mma16816(float* c, const uint32_t* a, const uint32_t* b) {
    asm volatile(
        "mma.sync.aligned.m16n8k16.row.col.f32.f16.f16.f32 "
        "{%0,%1,%2,%3}, {%4,%5,%6,%7}, {%8,%9}, {%0,%1,%2,%3};"
        : "+f"(c[0]), "+f"(c[1]), "+f"(c[2]), "+f"(c[3])
        : "r"(a[0]), "r"(a[1]), "r"(a[2]), "r"(a[3]), "r"(b[0]), "r"(b[1]));
}

// ---------------------------------------------------------------------------
// Fused prep: conv x->fp16 | pack+split weights | conv W_out->fp16
// Grid sections by blockIdx.x:
//   [0, 16384)              conv x           (4,194,304 float4)
//   [16384, 16384+1536)     pack weights     (393,216 elems) + biases
//   [16384+1536, +256)      conv W_out       (65,536 float4)
// ---------------------------------------------------------------------------
#define PREP_BX 16384
#define PREP_BP 1536
#define PREP_BW 256

__global__ __launch_bounds__(256)
void prep_kernel(const float* __restrict__ x,
                 const float* __restrict__ W_B, const float* __restrict__ b_B,
                 const float* __restrict__ W_X, const float* __restrict__ b_X,
                 const float* __restrict__ W_d, const float* __restrict__ b_d,
                 const float* __restrict__ W_t, const float* __restrict__ b_t,
                 const float* __restrict__ W_out) {
    const int bid = blockIdx.x;
    if (bid < PREP_BX) {
        int i = bid * 256 + threadIdx.x;           // float4 index into x
        float4 v = reinterpret_cast<const float4*>(x)[i];
        __half2 a = __floats2half2_rn(v.x, v.y);
        __half2 b = __floats2half2_rn(v.z, v.w);
        reinterpret_cast<__half2*>(g_xh)[2 * i]     = a;
        reinterpret_cast<__half2*>(g_xh)[2 * i + 1] = b;
    } else if (bid < PREP_BX + PREP_BP) {
        int i = (bid - PREP_BX) * 256 + threadIdx.x;   // element index
        int f = i >> 10, k = i & 1023;
        float v = 0.f;
        if      (f < OFF_X)     v = W_t[f * D_IN + k];
        else if (f < OFF_DECAY) v = W_X[(f - OFF_X) * D_IN + k];
        else if (f < 100)       v = W_d[(f - OFF_DECAY) * D_IN + k];
        else if (f < OFF_B)     v = 0.f;
        else                    v = W_B[(f - OFF_B) * D_IN + k];
        __half h = __float2half_rn(v);
        g_Whi[i] = h;
        g_Wlo[i] = __float2half_rn(v - __half2float(h));
        if (i < NFP) {
            float bv = 0.f;
            if      (i < OFF_X)     bv = b_t[i];
            else if (i < OFF_DECAY) bv = b_X[i - OFF_X];
            else if (i < 100)       bv = b_d[i - OFF_DECAY];
            else if (i < OFF_B)     bv = 0.f;
            else                    bv = b_B[i - OFF_B];
            g_bcat[i] = bv;
        }
    } else {
        int i = (bid - PREP_BX - PREP_BP) * 256 + threadIdx.x;  // float4 idx
        float4 v = reinterpret_cast<const float4*>(W_out)[i];
        __half2 a = __floats2half2_rn(v.x, v.y);
        __half2 b = __floats2half2_rn(v.z, v.w);
        reinterpret_cast<__half2*>(g_Woh)[2 * i]     = a;
        reinterpret_cast<__half2*>(g_Woh)[2 * i + 1] = b;
    }
}

// ---------------------------------------------------------------------------
// HMMA fp16 GEMM: C[m][n] = sum_k A[m,k]*B[n,k]
// Lo-pass (Blo) only for blockIdx.y < ny2 AND warp column wn==0 — i.e. the
// first 32 N-cols of the first N-block (the theta region).
// Tile 128x128, BK=32, 512 threads; warp grid 4(M) x 4(N), warp tile 32x32.
// 3-stage cp.async ring; rows padded to 80 B -> ldmatrix conflict-free.
// ---------------------------------------------------------------------------
#define ROWB 80                       // padded row stride in bytes (40 fp16)
#define TILEB (128 * ROWB)            // 10240 bytes per tile
#define NSTAGE 3

template<bool SILU, int NTILES>
__global__ __launch_bounds__(512, 1)
void mma_gemm(const __half* __restrict__ A,
              const __half* __restrict__ Bhi, const __half* __restrict__ Blo,
              const float* __restrict__ bias, float* __restrict__ C,
              int K, int ldc, int ny2) {
    constexpr int STAGEB = NTILES * TILEB;
    extern __shared__ __align__(128) char smem[];
    const uint32_t sb = smem_u32(smem);

    const bool two_pass = (NTILES == 3) && ((int)blockIdx.y < ny2);

    const int tid = threadIdx.x;
    const int wid = tid >> 5, lane = tid & 31;
    const int wm = wid & 3;            // 0..3  (M)  -> SMSP
    const int wn = wid >> 2;           // 0..3  (N)
    const int m0 = blockIdx.x * 128, n0 = blockIdx.y * 128;

    // cp.async: 512 chunks of 16B per tile per stage; 1 chunk/thread/tile
    const int cr = tid >> 2, ck = tid & 3;

    // ldmatrix lane addressing
    const int a_row = (lane & 7) + ((lane >> 3) & 1) * 8;   // 0..15
    const int a_kc  = lane >> 4;                            // 0..1
    const uint32_t a_base = (uint32_t)((wm * 32 + a_row) * ROWB + a_kc * 16);
    // packed-B x4: mats {j,k0},{j,k8},{j+1,k0},{j+1,k8}
    const int b_prow = (lane & 7) + ((lane >> 4) << 3);     // 0..15
    const int b_kc2  = (lane >> 3) & 1;
    const uint32_t b_base = (uint32_t)((wn * 32 + b_prow) * ROWB + b_kc2 * 16);

    float acc[2][4][4];
    #pragma unroll
    for (int i = 0; i < 2; i++)
        #pragma unroll
        for (int j = 0; j < 4; j++)
            #pragma unroll
            for (int q = 0; q < 4; q++) acc[i][j][q] = 0.f;

    const int nkb = K >> 5;

    auto load_stage = [&](int kb, int stage) {
        const uint32_t s0 = sb + stage * STAGEB;
        const int kofs = kb << 5;
        size_t ga = (size_t)(m0 + cr) * K + kofs + ck * 8;
        size_t gb = (size_t)(n0 + cr) * K + kofs + ck * 8;
        uint32_t so = (uint32_t)(cr * ROWB + ck * 16);
        CP_ASYNC16(s0 + 0 * TILEB + so, A   + ga);
        CP_ASYNC16(s0 + 1 * TILEB + so, Bhi + gb);
        if (NTILES == 3 && two_pass) CP_ASYNC16(s0 + 2 * TILEB + so, Blo + gb);
    };

    // Prologue: 2 stages in flight
    load_stage(0, 0); CP_COMMIT();
    if (nkb > 1) { load_stage(1, 1); CP_COMMIT(); }

    int stage = 0;
    for (int kb = 0; kb < nkb; kb++) {
        if (kb == nkb - 1) { CP_WAIT0(); } else { CP_WAIT1(); }
        __syncthreads();
        if (kb + 2 < nkb) {
            int ns = stage + 2; if (ns >= NSTAGE) ns -= NSTAGE;
            load_stage(kb + 2, ns);
            CP_COMMIT();
        }

        const uint32_t s0 = sb + stage * STAGEB;
        #pragma unroll
        for (int s = 0; s < 2; s++) {          // two k16 steps per BK=32
            uint32_t ah[2][4], bh[4][2];
            #pragma unroll
            for (int i = 0; i < 2; i++) {
                uint32_t ao = s0 + a_base + (uint32_t)(i * 16 * ROWB + s * 32);
                ldm_x4(ah[i], ao);
            }
            #pragma unroll
            for (int jj = 0; jj < 4; jj += 2) {
                uint32_t bo = s0 + 1 * TILEB + b_base + (uint32_t)(jj * 8 * ROWB + s * 32);
                uint32_t t4[4];
                ldm_x4(t4, bo);
                bh[jj][0] = t4[0]; bh[jj][1] = t4[1];
                bh[jj + 1][0] = t4[2]; bh[jj + 1][1] = t4[3];
            }
            #pragma unroll
            for (int i = 0; i < 2; i++)
                #pragma unroll
                for (int j = 0; j < 4; j++)
                    mma16816(acc[i][j], ah[i], bh[j]);
            if (NTILES == 3) {
                if (two_pass && wn == 0) {   // lo pass: theta cols only
                    uint32_t bl[4][2];
                    #pragma unroll
                    for (int jj = 0; jj < 4; jj += 2) {
                        uint32_t bo = s0 + 2 * TILEB + b_base + (uint32_t)(jj * 8 * ROWB + s * 32);
                        uint32_t t4[4];
                        ldm_x4(t4, bo);
                        bl[jj][0] = t4[0]; bl[jj][1] = t4[1];
                        bl[jj + 1][0] = t4[2]; bl[jj + 1][1] = t4[3];
                    }
                    #pragma unroll
                    for (int i = 0; i < 2; i++)
                        #pragma unroll
                        for (int j = 0; j < 4; j++)
                            mma16816(acc[i][j], ah[i], bl[j]);
                }
            }
        }
        stage++; if (stage >= NSTAGE) stage = 0;
    }

    // Epilogue
    const int tr = lane >> 2;            // 0..7
    const int tc = (lane & 3) * 2;       // 0,2,4,6
    #pragma unroll
    for (int i = 0; i < 2; i++) {
        #pragma unroll
        for (int j = 0; j < 4; j++) {
            int m = m0 + wm * 32 + i * 16 + tr;
            int n = n0 + wn * 32 + j * 8 + tc;
            float e0 = acc[i][j][0], e1 = acc[i][j][1];
            float e2 = acc[i][j][2], e3 = acc[i][j][3];
            if (SILU) {
                float bb0 = bias[n], bb1 = bias[n + 1];
                e0 += bb0; e1 += bb1; e2 += bb0; e3 += bb1;
                e0 = __fdividef(e0, 1.f + __expf(-e0));
                e1 = __fdividef(e1, 1.f + __expf(-e1));
                e2 = __fdividef(e2, 1.f + __expf(-e2));
                e3 = __fdividef(e3, 1.f + __expf(-e3));
            }
            float2* p0 = reinterpret_cast<float2*>(C + (size_t)m * ldc + n);
            float2* p1 = reinterpret_cast<float2*>(C + (size_t)(m + 8) * ldc + n);
            *p0 = make_float2(e0, e1);
            *p1 = make_float2(e2, e3);
        }
    }
}

// ---------------------------------------------------------------------------
// Elementwise: silu/sigmoid/rotary/decay*H -> H_new (fp32) + F (fp16 single)
// Uses the repacked column layout (theta|X|decay|pad|B).
// ---------------------------------------------------------------------------
__global__ __launch_bounds__(256)
void elementwise_kernel(const float* __restrict__ H, const int* __restrict__ layer_idx,
                        float* __restrict__ Hnew, __half* __restrict__ Fh) {
    const int token = blockIdx.x;
    const int b = token >> 12;
    const int l = token & 4095;
    const int t = threadIdx.x;

    __shared__ float sP[NFP];
    __shared__ float sB[NRF];
    __shared__ float sD[NN];
    __shared__ float sC[NN / 2];
    __shared__ float sS[NN / 2];
    __shared__ float sX[RR];

    for (int i = t; i < NFP; i += 256)
        sP[i] = g_P[(size_t)token * NFP + i] + g_bcat[i];
    __syncthreads();

    {   // silu of the 256 B-projection features (cols 128..383)
        float v = sP[OFF_B + t];
        sB[t] = __fdividef(v, 1.f + __expf(-v));
    }
    if (t < NN) {                       // decay sigmoid (64 distinct)
        float dv = sP[OFF_DECAY + t];
        sD[t] = __fdividef(1.f, 1.f + __expf(-dv));
    }
    if (t < NN / 2) {                   // rotary sincos (32 distinct)
        const float scale = (float)(*layer_idx + 1);
        float th = sP[OFF_THETA + t] * scale;
        float cs, sn;
        __sincosf(th, &sn, &cs);
        sC[t] = cs; sS[t] = sn;
    }
    if (t < RR) {                       // X_r silu (4 distinct)
        float xv = sP[OFF_X + t];
        sX[t] = __fdividef(xv, 1.f + __expf(-xv));
    }
    __syncthreads();

    const int r = t >> 6;
    const int n = t & 63;
    const int j = n >> 1;

    const float x1 = sB[(n & ~1) * RR + r];
    const float x2 = sB[(n |  1) * RR + r];
    const float rot = (n & 1) ? (x1 * sS[j] + x2 * sC[j]) : (x1 * sC[j] - x2 * sS[j]);

    const size_t hidx = (((size_t)(b * RR + r) * LL + l) * NN) + n;
    const float hnew = sD[n] * H[hidx] + rot * sX[r];

    Hnew[hidx] = hnew;
    Fh[(size_t)token * NRF + (r * NN + n)] = __float2half_rn(hnew);
}

// ---------------------------------------------------------------------------
extern "C" void kernel_launch(void* const* d_in, const int* in_sizes, int n_in,
                              void* d_out, int out_size) {
    const float* x     = (const float*)d_in[0];
    const float* H     = (const float*)d_in[1];
    const float* W_B   = (const float*)d_in[2];
    const float* b_B   = (const float*)d_in[3];
    const float* W_X   = (const float*)d_in[4];
    const float* b_X   = (const float*)d_in[5];
    const float* W_d   = (const float*)d_in[6];
    const float* b_d   = (const float*)d_in[7];
    const float* W_t   = (const float*)d_in[8];
    const float* b_t   = (const float*)d_in[9];
    const float* W_out = (const float*)d_in[10];
    const float* b_out = (const float*)d_in[11];
    const int*   lidx  = (const int*)d_in[12];

    const size_t HE = (size_t)BBATCH * RR * LL * NN;   //  4,194,304
    const size_t OE = (size_t)BBATCH * LL * D_IN;      // 16,777,216

    float* hnew_dst;
    float* out_dst;
    if ((size_t)out_size >= HE + OE) {
        hnew_dst = (float*)d_out;
        out_dst  = (float*)d_out + HE;
    } else {
        cudaGetSymbolAddress((void**)&hnew_dst, g_Hscratch);
        out_dst  = (float*)d_out;
    }

    __half *xh, *Whi, *Wlo, *Fh, *Woh;
    float* P_ptr;
    cudaGetSymbolAddress((void**)&xh,   g_xh);
    cudaGetSymbolAddress((void**)&Whi,  g_Whi);
    cudaGetSymbolAddress((void**)&Wlo,  g_Wlo);
    cudaGetSymbolAddress((void**)&Fh,   g_Fh);
    cudaGetSymbolAddress((void**)&Woh,  g_Woh);
    cudaGetSymbolAddress((void**)&P_ptr, g_P);

    const int SMEM_G1 = NSTAGE * 3 * TILEB;  // 92160 (A,Bhi,Blo)
    const int SMEM_G2 = NSTAGE * 2 * TILEB;  // 61440 (A,Bhi)
    cudaFuncSetAttribute((const void*)mma_gemm<false, 3>,
                         cudaFuncAttributeMaxDynamicSharedMemorySize, SMEM_G1);
    cudaFuncSetAttribute((const void*)mma_gemm<true, 2>,
                         cudaFuncAttributeMaxDynamicSharedMemorySize, SMEM_G2);

    // 1) fused prep: conv x | pack+split weights | conv W_out
    prep_kernel<<<PREP_BX + PREP_BP + PREP_BW, 256>>>(
        x, W_B, b_B, W_X, b_X, W_d, b_d, W_t, b_t, W_out);

    // 2) projection GEMM: P[16384 x 384] = x @ Wcat^T
    //    N-block 0 (theta|X|decay): lo pass only on theta cols (wn==0)
    //    N-blocks 1,2 (B_proj): 1-pass fp16
    mma_gemm<false, 3><<<dim3(M_TOK / 128, NFP / 128), 512, SMEM_G1>>>(
        xh, Whi, Wlo, nullptr, P_ptr, D_IN, NFP, /*ny2=*/1);

    // 3) elementwise -> H_new + F (fp16)
    elementwise_kernel<<<M_TOK, 256>>>(H, lidx, hnew_dst, Fh);

    // 4) output GEMM: out[16384 x 1024] = silu(F @ W_out^T + b_out)  (1-pass)
    mma_gemm<true, 2><<<dim3(M_TOK / 128, D_IN / 128), 512, SMEM_G2>>>(
        Fh, Woh, nullptr, b_out, out_dst, NRF, D_IN, /*ny2=*/0);
}